// round 9
// baseline (speedup 1.0000x reference)
#include <cuda_runtime.h>
#include <cuda_bf16.h>
#include <math.h>
#include <stdint.h>

// ---------------------------------------------------------------------------
// Problem constants (B=2, H=W=64, C=256, nh=4, hd=64, k=7)
// ---------------------------------------------------------------------------
#define NTOK   8192
#define CDIM   256
#define GK     256
#define QKVN   768
#define FFN    512
#define KS     7
#define KK     49

// ---------------------------------------------------------------------------
// Scratch (__device__ globals; allocation forbidden)
// ---------------------------------------------------------------------------
__device__ __nv_bfloat16 g_qkv [NTOK * QKVN];
__device__ __nv_bfloat16 g_attn[NTOK * CDIM];
__device__ float         g_x1  [NTOK * CDIM];
__device__ __nv_bfloat16 g_ffh [NTOK * FFN];
__device__ __nv_bfloat16 g_wqkvT[QKVN * GK];
__device__ __nv_bfloat16 g_wprojT[CDIM * GK];
__device__ __nv_bfloat16 g_ff1T [FFN  * GK];
__device__ __nv_bfloat16 g_ff2T [CDIM * GK];
__device__ float2        g_rope[64 * 64];       // [pos][j] = (cos, sin)

// ---------------------------------------------------------------------------
// PTX helpers
// ---------------------------------------------------------------------------
__device__ __forceinline__ uint32_t smem_u32(const void* p) {
    uint32_t a;
    asm("{ .reg .u64 t; cvta.to.shared.u64 t, %1; cvt.u32.u64 %0, t; }"
        : "=r"(a) : "l"(p));
    return a;
}
#define LDMATRIX_X4(r0, r1, r2, r3, a) \
    asm volatile("ldmatrix.sync.aligned.m8n8.x4.shared.b16 {%0,%1,%2,%3}, [%4];" \
                 : "=r"(r0), "=r"(r1), "=r"(r2), "=r"(r3) : "r"(a))
#define LDMATRIX_X4_TRANS(r0, r1, r2, r3, a) \
    asm volatile("ldmatrix.sync.aligned.m8n8.x4.trans.shared.b16 {%0,%1,%2,%3}, [%4];" \
                 : "=r"(r0), "=r"(r1), "=r"(r2), "=r"(r3) : "r"(a))
#define MMA_BF16(d, a, b) \
    asm volatile("mma.sync.aligned.m16n8k16.row.col.f32.bf16.bf16.f32 " \
                 "{%0,%1,%2,%3}, {%4,%5,%6,%7}, {%8,%9}, {%0,%1,%2,%3};" \
                 : "+f"((d)[0]), "+f"((d)[1]), "+f"((d)[2]), "+f"((d)[3]) \
                 : "r"((a)[0]), "r"((a)[1]), "r"((a)[2]), "r"((a)[3]), \
                   "r"((b)[0]), "r"((b)[1]))
#define CP_ASYNC16(dst, src) \
    asm volatile("cp.async.cg.shared.global [%0], [%1], 16;" :: "r"(dst), "l"(src))
#define CP_COMMIT() asm volatile("cp.async.commit_group;" ::: "memory")
#define CP_WAIT(n)  asm volatile("cp.async.wait_group %0;" :: "n"(n) : "memory")

__device__ __forceinline__ uint32_t swz(uint32_t off) { return off ^ ((off >> 3) & 0x70); }
__device__ __forceinline__ uint32_t packbf(float a, float b) {
    __nv_bfloat162 h = __floats2bfloat162_rn(a, b);
    return *reinterpret_cast<uint32_t*>(&h);
}

// ---------------------------------------------------------------------------
// Fused weight convert+transpose + rope table (one launch).
// grid (57, 8): bx 0..55 weight tiles, bx == 56 fills g_rope.
// ---------------------------------------------------------------------------
__global__ void transpose_all_kernel(const float* __restrict__ w0, __nv_bfloat16* __restrict__ o0,
                                     const float* __restrict__ w1, __nv_bfloat16* __restrict__ o1,
                                     const float* __restrict__ w2, __nv_bfloat16* __restrict__ o2,
                                     const float* __restrict__ w3, __nv_bfloat16* __restrict__ o3)
{
    const int bx = blockIdx.x;
    const int tx = threadIdx.x, ty = threadIdx.y;      // 32 x 8

    if (bx == 56) {                                    // rope table: 4096 entries
        const int base = blockIdx.y * 512;
        for (int e = base + ty * 32 + tx; e < base + 512; e += 256) {
            const int pos = e >> 6, j = e & 63;
            const float inv = exp2f((float)j * (-13.28771237954945f / 64.0f));
            float s, c;
            sincosf((float)pos * inv, &s, &c);
            g_rope[e] = make_float2(c, s);
        }
        return;
    }

    const float* w; __nv_bfloat16* o; int N, nb;
    if      (bx < 24) { w = w0; o = o0; N = QKVN; nb = bx;      }
    else if (bx < 32) { w = w1; o = o1; N = CDIM; nb = bx - 24; }
    else if (bx < 48) { w = w2; o = o2; N = FFN;  nb = bx - 32; }
    else              { w = w3; o = o3; N = CDIM; nb = bx - 48; }

    __shared__ float t[32][33];
    const int n0 = nb * 32, k0 = blockIdx.y * 32;
    #pragma unroll
    for (int i = 0; i < 32; i += 8)
        t[ty + i][tx] = w[(size_t)(k0 + ty + i) * N + n0 + tx];
    __syncthreads();
    #pragma unroll
    for (int i = 0; i < 32; i += 8)
        o[(size_t)(n0 + ty + i) * GK + k0 + tx] = __float2bfloat16(t[tx][ty + i]);
}

// ---------------------------------------------------------------------------
// Fused mma.sync bf16 GEMM.
// PRE = 0: A is bf16, cp.async ring for A and B (layout: stage*(16K+BNB)).
// PRE = 1: A = rope2d(rmsnorm(fp32 src, nw))   -> A-full smem (64KB) + B ring.
// PRE = 2: A = rmsnorm(fp32 src, nw)           -> same.
// PRE = 3: A = geglu(bf16 ffh src)             -> same.
// mode: 0 = bf16 out, 2 = fp32 +bias+residual, 3 = bf16 +bias
// ---------------------------------------------------------------------------
template<int BN, int PRE>
__global__ __launch_bounds__(256, 2)
void gemm_fused(const void* __restrict__ Asrc,
                const __nv_bfloat16* __restrict__ Bt,
                const float* __restrict__ bias,
                const float* __restrict__ residual,
                const float* __restrict__ nw,
                float* __restrict__ C,
                __nv_bfloat16* __restrict__ Cb,
                int N, int mode)
{
    constexpr int WM = (BN == 128) ? 2 : 4;
    constexpr int MT = (BN == 128) ? 4 : 2;
    constexpr int BITERS = BN / 32;
    constexpr uint32_t BNB = (uint32_t)BN * 128u;      // B chunk bytes
    constexpr uint32_t STG = 16384u + BNB;             // PRE=0 ring stage stride
    constexpr uint32_t BOFF = 65536u;                  // PRE!=0 B ring base

    extern __shared__ __align__(1024) char smem[];
    const uint32_t sb = smem_u32(smem);
    const int tid  = threadIdx.x;
    const int wid  = tid >> 5;
    const int lane = tid & 31;
    const int bm   = blockIdx.y * 128;
    const int bn   = blockIdx.x * BN;
    const int wm   = wid % WM;
    const int wn   = wid / WM;
    const int lrow = tid >> 3;
    const int lch  = tid & 7;

    #define LOAD_AB(kc, stage) do {                                              \
        const uint32_t s0 = (uint32_t)(stage) * STG;                             \
        _Pragma("unroll")                                                        \
        for (int it = 0; it < 4; it++) {                                         \
            const int r_ = it * 32 + lrow;                                       \
            uint32_t off = swz((uint32_t)r_ * 128u + (uint32_t)lch * 16u);       \
            CP_ASYNC16(sb + s0 + off,                                            \
                (const __nv_bfloat16*)Asrc + (size_t)(bm + r_) * GK + (kc) * 64 + lch * 8); \
        }                                                                        \
        _Pragma("unroll")                                                        \
        for (int it = 0; it < BITERS; it++) {                                    \
            const int r_ = it * 32 + lrow;                                       \
            uint32_t off = swz((uint32_t)r_ * 128u + (uint32_t)lch * 16u);       \
            CP_ASYNC16(sb + s0 + 16384u + off,                                   \
                       Bt + (size_t)(bn + r_) * GK + (kc) * 64 + lch * 8);       \
        }                                                                        \
        CP_COMMIT();                                                             \
    } while (0)

    #define LOAD_B(kc, stage) do {                                               \
        const uint32_t s0 = BOFF + (uint32_t)(stage) * BNB;                      \
        _Pragma("unroll")                                                        \
        for (int it = 0; it < BITERS; it++) {                                    \
            const int r_ = it * 32 + lrow;                                       \
            uint32_t off = swz((uint32_t)r_ * 128u + (uint32_t)lch * 16u);       \
            CP_ASYNC16(sb + s0 + off,                                            \
                       Bt + (size_t)(bn + r_) * GK + (kc) * 64 + lch * 8);       \
        }                                                                        \
        CP_COMMIT();                                                             \
    } while (0)

    if (PRE == 0) {
        LOAD_AB(0, 0);
        LOAD_AB(1, 1);
    } else {
        LOAD_B(0, 0);
        LOAD_B(1, 1);

        // ---- A prep: 2 threads per row (half = 128 cols each) ----
        const int row  = tid >> 1;
        const int half = tid & 1;

        if (PRE == 1 || PRE == 2) {
            const float* Ax = (const float*)Asrc;
            const float4* src = reinterpret_cast<const float4*>(
                Ax + (size_t)(bm + row) * GK + half * 128);
            float ss = 0.0f;
            #pragma unroll 8
            for (int i = 0; i < 32; i++) {
                float4 v = src[i];
                ss += v.x * v.x + v.y * v.y + v.z * v.z + v.w * v.w;
            }
            ss += __shfl_xor_sync(0xffffffffu, ss, 1);
            const float r = rsqrtf(ss * (1.0f / GK) + 1e-6f);

            const int grow = bm + row;
            const float2* rope = &g_rope[(half ? (grow & 63) : ((grow >> 6) & 63)) * 64];
            const float2* wv = reinterpret_cast<const float2*>(nw + half * 128);

            #pragma unroll 8
            for (int i = 0; i < 32; i++) {
                float4 v = src[i];
                const float2 w0 = wv[2 * i], w1 = wv[2 * i + 1];
                float a0 = v.x * r * w0.x, b0 = v.y * r * w0.y;
                float a1 = v.z * r * w1.x, b1 = v.w * r * w1.y;
                if (PRE == 1) {
                    const float2 c0 = rope[2 * i], c1 = rope[2 * i + 1];
                    const float t0 = a0 * c0.x - b0 * c0.y, u0 = a0 * c0.y + b0 * c0.x;
                    const float t1 = a1 * c1.x - b1 * c1.y, u1 = a1 * c1.y + b1 * c1.x;
                    a0 = t0; b0 = u0; a1 = t1; b1 = u1;
                }
                const int col = half * 128 + i * 4;
                uint32_t off = swz((uint32_t)(col >> 6) * 16384u
                                   + (uint32_t)row * 128u + (uint32_t)(col & 63) * 2u);
                uint2 st;
                st.x = packbf(a0, b0);
                st.y = packbf(a1, b1);
                *reinterpret_cast<uint2*>(smem + off) = st;
            }
        } else {    // PRE == 3: geglu
            const __nv_bfloat16* F = (const __nv_bfloat16*)Asrc;
            const __nv_bfloat16* gp = F + (size_t)(bm + row) * FFN + half * 128;
            #pragma unroll 4
            for (int i = 0; i < 16; i++) {
                const uint4 gv = reinterpret_cast<const uint4*>(gp)[i];
                const uint4 vv = reinterpret_cast<const uint4*>(gp + CDIM)[i];
                const __nv_bfloat162* g2 = reinterpret_cast<const __nv_bfloat162*>(&gv);
                const __nv_bfloat162* v2 = reinterpret_cast<const __nv_bfloat162*>(&vv);
                uint4 st;
                uint32_t* stp = reinterpret_cast<uint32_t*>(&st);
                #pragma unroll
                for (int k = 0; k < 4; k++) {
                    const float2 gg = __bfloat1622float2(g2[k]);
                    const float2 vf = __bfloat1622float2(v2[k]);
                    const float e0 = 0.5f * gg.x * (1.0f + erff(gg.x * 0.70710678118654752f));
                    const float e1 = 0.5f * gg.y * (1.0f + erff(gg.y * 0.70710678118654752f));
                    stp[k] = packbf(e0 * vf.x, e1 * vf.y);
                }
                const int col = half * 128 + i * 8;
                uint32_t off = swz((uint32_t)(col >> 6) * 16384u
                                   + (uint32_t)row * 128u + (uint32_t)(col & 63) * 2u);
                *reinterpret_cast<uint4*>(smem + off) = st;
            }
        }
    }

    float acc[MT][4][4] = {};
    const int mtx = lane >> 3;
    const int l7  = lane & 7;

    #pragma unroll
    for (int kc = 0; kc < 4; kc++) {
        if (kc < 3) CP_WAIT(1); else CP_WAIT(0);
        __syncthreads();

        const uint32_t sA = (PRE == 0) ? (sb + (uint32_t)(kc & 1) * STG)
                                       : (sb + (uint32_t)kc * 16384u);
        const uint32_t sB = (PRE == 0) ? (sA + 16384u)
                                       : (sb + BOFF + (uint32_t)(kc & 1) * BNB);

        #pragma unroll
        for (int s16 = 0; s16 < 4; s16++) {
            const int chunk0 = s16 * 2;

            uint32_t af[MT][4];
            #pragma unroll
            for (int mt = 0; mt < MT; mt++) {
                const int row   = wm * (MT * 16) + mt * 16 + (mtx & 1) * 8 + l7;
                const int chunk = chunk0 + (mtx >> 1);
                LDMATRIX_X4(af[mt][0], af[mt][1], af[mt][2], af[mt][3],
                            sA + swz((uint32_t)row * 128u + (uint32_t)chunk * 16u));
            }
            uint32_t bf[4][2];
            #pragma unroll
            for (int pair = 0; pair < 2; pair++) {
                const int nrow  = wn * 32 + pair * 16 + (mtx >> 1) * 8 + l7;
                const int chunk = chunk0 + (mtx & 1);
                LDMATRIX_X4(bf[pair * 2][0], bf[pair * 2][1],
                            bf[pair * 2 + 1][0], bf[pair * 2 + 1][1],
                            sB + swz((uint32_t)nrow * 128u + (uint32_t)chunk * 16u));
            }
            #pragma unroll
            for (int mt = 0; mt < MT; mt++)
                #pragma unroll
                for (int nt = 0; nt < 4; nt++)
                    MMA_BF16(acc[mt][nt], af[mt], bf[nt]);
        }
        __syncthreads();
        if (kc < 2) {
            if (PRE == 0) LOAD_AB(kc + 2, kc & 1);
            else          LOAD_B(kc + 2, kc & 1);
        }
    }
    #undef LOAD_AB
    #undef LOAD_B

    const int rbase = bm + wm * (MT * 16) + (lane >> 2);
    const int cbase = bn + wn * 32 + (lane & 3) * 2;
    #pragma unroll
    for (int mt = 0; mt < MT; mt++) {
        #pragma unroll
        for (int half = 0; half < 2; half++) {
            const int row = rbase + mt * 16 + half * 8;
            #pragma unroll
            for (int nt = 0; nt < 4; nt++) {
                const int col = cbase + nt * 8;
                float ox = acc[mt][nt][half * 2];
                float oy = acc[mt][nt][half * 2 + 1];
                const size_t idx = (size_t)row * N + col;
                if (mode == 0) {
                    *reinterpret_cast<__nv_bfloat162*>(&Cb[idx]) =
                        __floats2bfloat162_rn(ox, oy);
                } else {
                    ox += bias[col];
                    oy += bias[col + 1];
                    if (mode == 2) {
                        const float2 rr = *reinterpret_cast<const float2*>(&residual[idx]);
                        ox += rr.x; oy += rr.y;
                        *reinterpret_cast<float2*>(&C[idx]) = make_float2(ox, oy);
                    } else {   // mode == 3
                        *reinterpret_cast<__nv_bfloat162*>(&Cb[idx]) =
                            __floats2bfloat162_rn(ox, oy);
                    }
                }
            }
        }
    }
}

// ---------------------------------------------------------------------------
// Tiled tensor-core neighborhood attention (unchanged from R8).
// ---------------------------------------------------------------------------
#define AT_Q    0
#define AT_K    8192
#define AT_V    36864
#define AT_RED  8192
#define AT_MAX  65536
#define AT_SUM  66048
#define AT_SIZE 66560
#define REDW    68

__global__ __launch_bounds__(256, 2)
void attn_mma_kernel(const __nv_bfloat16* __restrict__ qkv,
                     __nv_bfloat16* __restrict__ out)
{
    extern __shared__ __align__(1024) char smem[];
    const uint32_t sb = smem_u32(smem);
    float* smax = reinterpret_cast<float*>(smem + AT_MAX);
    float* ssum = reinterpret_cast<float*>(smem + AT_SUM);
    float* sred = reinterpret_cast<float*>(smem + AT_RED);

    const int tid  = threadIdx.x;
    const int wid  = tid >> 5;
    const int lane = tid & 31;
    const int head = blockIdx.y;
    const int b    = blockIdx.z;
    const int ty0  = (blockIdx.x >> 3) * 8;
    const int tx0  = (blockIdx.x & 7) * 8;
    const int ny0  = min(max(ty0 - 3, 0), 50);
    const int nx0  = min(max(tx0 - 3, 0), 50);

    const __nv_bfloat16* base = qkv + (size_t)b * 4096 * QKVN + head * 64;

    #pragma unroll
    for (int i = 0; i < 2; i++) {
        const int idx = i * 256 + tid;
        const int m = idx >> 3, ch = idx & 7;
        const int y = ty0 + (m >> 3), x = tx0 + (m & 7);
        uint32_t off = swz((uint32_t)m * 128u + (uint32_t)ch * 16u);
        CP_ASYNC16(sb + AT_Q + off, base + (size_t)(y * 64 + x) * QKVN + ch * 8);
    }
    CP_COMMIT();
    #pragma unroll
    for (int i = 0; i < 7; i++) {
        const int idx = i * 256 + tid;
        const int kv = idx >> 3, ch = idx & 7;
        const int r = kv >> 4, c = kv & 15;
        uint32_t off = swz((uint32_t)kv * 128u + (uint32_t)ch * 16u);
        if (c < 14)
            CP_ASYNC16(sb + AT_K + off,
                       base + (size_t)((ny0 + r) * 64 + nx0 + c) * QKVN + CDIM + ch * 8);
        else
            *reinterpret_cast<uint4*>(smem + AT_K + off) = make_uint4(0, 0, 0, 0);
    }
    CP_COMMIT();
    #pragma unroll
    for (int i = 0; i < 7; i++) {
        const int idx = i * 256 + tid;
        const int kv = idx >> 3, ch = idx & 7;
        const int r = kv >> 4, c = kv & 15;
        uint32_t off = swz((uint32_t)kv * 128u + (uint32_t)ch * 16u);
        if (c < 14)
            CP_ASYNC16(sb + AT_V + off,
                       base + (size_t)((ny0 + r) * 64 + nx0 + c) * QKVN + 2 * CDIM + ch * 8);
        else
            *reinterpret_cast<uint4*>(smem + AT_V + off) = make_uint4(0, 0, 0, 0);
    }
    CP_COMMIT();

    const int wm  = wid & 3;
    const int wn  = wid >> 2;
    const int mtx = lane >> 3;
    const int l7  = lane & 7;

    CP_WAIT(1);
    __syncthreads();

    uint32_t af[4][4];
    #pragma unroll
    for (int k16 = 0; k16 < 4; k16++) {
        const int row   = wm * 16 + (mtx & 1) * 8 + l7;
        const int chunk = k16 * 2 + (mtx >> 1);
        LDMATRIX_X4(af[k16][0], af[k16][1], af[k16][2], af[k16][3],
                    sb + AT_Q + swz((uint32_t)row * 128u + (uint32_t)chunk * 16u));
    }

    float acc[14][4] = {};
    #pragma unroll
    for (int k16 = 0; k16 < 4; k16++) {
        #pragma unroll
        for (int grp = 0; grp < 2; grp++) {
            const int nt0    = grp * 8;
            const int npairs = grp ? 3 : 4;
            uint32_t bf[8][2];
            #pragma unroll
            for (int pair = 0; pair < 4; pair++) {
                if (pair < npairs) {
                    const int nrow  = wn * 112 + (nt0 + pair * 2) * 8 + (mtx >> 1) * 8 + l7;
                    const int chunk = k16 * 2 + (mtx & 1);
                    LDMATRIX_X4(bf[pair * 2][0], bf[pair * 2][1],
                                bf[pair * 2 + 1][0], bf[pair * 2 + 1][1],
                                sb + AT_K + swz((uint32_t)nrow * 128u + (uint32_t)chunk * 16u));
                }
            }
            const int ntiles = grp ? 6 : 8;
            #pragma unroll
            for (int j = 0; j < 8; j++)
                if (j < ntiles)
                    MMA_BF16(acc[nt0 + j], af[k16], bf[j]);
        }
    }

    const int row0 = wm * 16 + (lane >> 2);
    const int row1 = row0 + 8;
    const int y_a = ty0 + (row0 >> 3), x_a = tx0 + (row0 & 7);
    const int y_b = ty0 + (row1 >> 3), x_b = tx0 + (row1 & 7);
    const int rlo_a = min(max(y_a - 3, 0), 57) - ny0;
    const int clo_a = min(max(x_a - 3, 0), 57) - nx0;
    const int rlo_b = min(max(y_b - 3, 0), 57) - ny0;
    const int clo_b = min(max(x_b - 3, 0), 57) - nx0;

    uint32_t vm_a = 0, vm_b = 0;
    #pragma unroll
    for (int nt = 0; nt < 14; nt++) {
        #pragma unroll
        for (int j = 0; j < 2; j++) {
            const int n = wn * 112 + nt * 8 + (lane & 3) * 2 + j;
            const int r = n >> 4, c = n & 15;
            if (c < 14 && (unsigned)(r - rlo_a) < 7u && (unsigned)(c - clo_a) < 7u)
                vm_a |= 1u << (nt * 2 + j);
            if (c < 14 && (unsigned)(r - rlo_b) < 7u && (unsigned)(c - clo_b) < 7u)
                vm_b |= 1u << (nt * 2 + j);
        }
    }

    float mx_a = -3e38f, mx_b = -3e38f;
    #pragma unroll
    for (int nt = 0; nt < 14; nt++) {
        #pragma unroll
        for (int j = 0; j < 2; j++) {
            if (vm_a & (1u << (nt * 2 + j))) mx_a = fmaxf(mx_a, acc[nt][j]);
            if (vm_b & (1u << (nt * 2 + j))) mx_b = fmaxf(mx_b, acc[nt][2 + j]);
        }
    }
    mx_a = fmaxf(mx_a, __shfl_xor_sync(0xffffffffu, mx_a, 1));
    mx_a = fmaxf(mx_a, __shfl_xor_sync(0xffffffffu, mx_a, 2));
    mx_b = fmaxf(mx_b, __shfl_xor_sync(0xffffffffu, mx_b, 1));
    mx_b = fmaxf(mx_b, __shfl_xor_sync(0xffffffffu, mx_b, 2));
    if ((lane & 3) == 0) {
        smax[row0 * 2 + wn] = mx_a;
        smax[row1 * 2 + wn] = mx_b;
    }
    __syncthreads();
    const float M_a = fmaxf(smax[row0 * 2], smax[row0 * 2 + 1]);
    const float M_b = fmaxf(smax[row1 * 2], smax[row1 * 2 + 1]);

    const float SC = 0.18033688011112042f;
    float sm_a = 0.0f, sm_b = 0.0f;
    #pragma unroll
    for (int nt = 0; nt < 14; nt++) {
        #pragma unroll
        for (int j = 0; j < 2; j++) {
            float ea = (vm_a & (1u << (nt * 2 + j)))
                     ? exp2f((acc[nt][j] - M_a) * SC) : 0.0f;
            float eb = (vm_b & (1u << (nt * 2 + j)))
                     ? exp2f((acc[nt][2 + j] - M_b) * SC) : 0.0f;
            acc[nt][j] = ea; acc[nt][2 + j] = eb;
            sm_a += ea; sm_b += eb;
        }
    }
    sm_a += __shfl_xor_sync(0xffffffffu, sm_a, 1);
    sm_a += __shfl_xor_sync(0xffffffffu, sm_a, 2);
    sm_b += __shfl_xor_sync(0xffffffffu, sm_b, 1);
    sm_b += __shfl_xor_sync(0xffffffffu, sm_b, 2);
    if ((lane & 3) == 0) {
        ssum[row0 * 2 + wn] = sm_a;
        ssum[row1 * 2 + wn] = sm_b;
    }

    uint32_t pf[7][4];
    #pragma unroll
    for (int s = 0; s < 7; s++) {
        pf[s][0] = packbf(acc[2 * s][0],     acc[2 * s][1]);
        pf[s][1] = packbf(acc[2 * s][2],     acc[2 * s][3]);
        pf[s][2] = packbf(acc[2 * s + 1][0], acc[2 * s + 1][1]);
        pf[s][3] = packbf(acc[2 * s + 1][2], acc[2 * s + 1][3]);
    }

    CP_WAIT(0);
    __syncthreads();

    float accO[8][4] = {};
    #pragma unroll
    for (int s = 0; s < 7; s++) {
        uint32_t vf[8][2];
        #pragma unroll
        for (int g2 = 0; g2 < 4; g2++) {
            const int kvrow = (wn * 7 + s) * 16 + (lane & 15);
            const int colb  = (g2 * 16 + (lane >> 4) * 8) * 2;
            LDMATRIX_X4_TRANS(vf[g2 * 2][0], vf[g2 * 2][1],
                              vf[g2 * 2 + 1][0], vf[g2 * 2 + 1][1],
                              sb + AT_V + swz((uint32_t)kvrow * 128u + (uint32_t)colb));
        }
        #pragma unroll
        for (int nt = 0; nt < 8; nt++)
            MMA_BF16(accO[nt], pf[s], vf[nt]);
    }

    if (wn == 1) {
        #pragma unroll
        for (int nt = 0; nt < 8; nt++) {
            const int col = nt * 8 + (lane & 3) * 2;
            *reinterpret_cast<float2*>(&sred[row0 * REDW + col]) =
                make_float2(accO[nt][0], accO[nt][1]);
            *reinterpret_cast<float2*>(&sred[row1 * REDW + col]) =
                make_float2(accO[nt][2], accO[nt][3]);
        }
    }
    __syncthreads();

    if (wn == 0) {
        const float inv_a = 1.0f / (ssum[row0 * 2] + ssum[row0 * 2 + 1]);
        const float inv_b = 1.0f / (ssum[row1 * 2] + ssum[row1 * 2 + 1]);
        const size_t t_a = (size_t)b * 4096 + (size_t)(y_a * 64 + x_a);
        const size_t t_b = (size_t)b * 4096 + (size_t)(y_b * 64 + x_b);
        #pragma unroll
        for (int nt = 0; nt < 8; nt++) {
            const int col = nt * 8 + (lane & 3) * 2;
            const float2 ra = *reinterpret_cast<const float2*>(&sred[row0 * REDW + col]);
            const float2 rb = *reinterpret_cast<const float2*>(&sred[row1 * REDW + col]);
            *reinterpret_cast<__nv_bfloat162*>(out + t_a * CDIM + head * 64 + col) =
                __floats2bfloat162_rn((accO[nt][0] + ra.x) * inv_a,
                                      (accO[nt][1] + ra.y) * inv_a);
            *reinterpret_cast<__nv_bfloat162*>(out + t_b * CDIM + head * 64 + col) =
                __floats2bfloat162_rn((accO[nt][2] + rb.x) * inv_b,
                                      (accO[nt][3] + rb.y) * inv_b);
        }
    }
}

// ---------------------------------------------------------------------------
// Launch: 6 kernels total.
// ---------------------------------------------------------------------------
#define SMSZ_P0_64   49152     // PRE=0, BN=64:  2*(16K + 8K)
#define SMSZ_P12_128 98304     // PRE=1/2, BN=128: 64K A + 2*16K B
#define SMSZ_P3_64   81920     // PRE=3, BN=64:  64K A + 2*8K B

extern "C" void kernel_launch(void* const* d_in, const int* in_sizes, int n_in,
                              void* d_out, int out_size)
{
    const float* x       = (const float*)d_in[0];
    const float* norm1_w = (const float*)d_in[1];
    const float* norm2_w = (const float*)d_in[2];
    const float* w_qkv   = (const float*)d_in[3];
    const float* w_proj  = (const float*)d_in[4];
    const float* b_proj  = (const float*)d_in[5];
    const float* ff1_w   = (const float*)d_in[6];
    const float* ff1_b   = (const float*)d_in[7];
    const float* ff2_w   = (const float*)d_in[8];
    const float* ff2_b   = (const float*)d_in[9];
    float* out = (float*)d_out;

    __nv_bfloat16 *p_qkv, *p_attn, *p_ffh;
    __nv_bfloat16 *p_wqkvT, *p_wprojT, *p_ff1T, *p_ff2T;
    float *p_x1;
    cudaGetSymbolAddress((void**)&p_qkv,    g_qkv);
    cudaGetSymbolAddress((void**)&p_attn,   g_attn);
    cudaGetSymbolAddress((void**)&p_x1,     g_x1);
    cudaGetSymbolAddress((void**)&p_ffh,    g_ffh);
    cudaGetSymbolAddress((void**)&p_wqkvT,  g_wqkvT);
    cudaGetSymbolAddress((void**)&p_wprojT, g_wprojT);
    cudaGetSymbolAddress((void**)&p_ff1T,   g_ff1T);
    cudaGetSymbolAddress((void**)&p_ff2T,   g_ff2T);

    cudaFuncSetAttribute(gemm_fused<128, 1>,
                         cudaFuncAttributeMaxDynamicSharedMemorySize, SMSZ_P12_128);
    cudaFuncSetAttribute(gemm_fused<128, 2>,
                         cudaFuncAttributeMaxDynamicSharedMemorySize, SMSZ_P12_128);
    cudaFuncSetAttribute(gemm_fused<64, 0>,
                         cudaFuncAttributeMaxDynamicSharedMemorySize, SMSZ_P0_64);
    cudaFuncSetAttribute(gemm_fused<64, 3>,
                         cudaFuncAttributeMaxDynamicSharedMemorySize, SMSZ_P3_64);
    cudaFuncSetAttribute(attn_mma_kernel,
                         cudaFuncAttributeMaxDynamicSharedMemorySize, AT_SIZE);

    // 1. weight transposes + rope table
    transpose_all_kernel<<<dim3(57, 8), dim3(32, 8)>>>(
        w_qkv, p_wqkvT, w_proj, p_wprojT, ff1_w, p_ff1T, ff2_w, p_ff2T);

    // 2. qkv = rope2d(rmsnorm(x, n1)) @ w_qkv        (fused A prep, bf16 out)
    gemm_fused<128, 1><<<dim3(QKVN / 128, NTOK / 128), 256, SMSZ_P12_128>>>(
        x, p_wqkvT, nullptr, nullptr, norm1_w, nullptr, p_qkv, QKVN, 0);

    // 3. attention -> bf16
    attn_mma_kernel<<<dim3(64, 4, 2), 256, AT_SIZE>>>(p_qkv, p_attn);

    // 4. x1 = x + attn @ w_proj + b_proj             (fp32)
    gemm_fused<64, 0><<<dim3(CDIM / 64, NTOK / 128), 256, SMSZ_P0_64>>>(
        p_attn, p_wprojT, b_proj, x, nullptr, p_x1, nullptr, CDIM, 2);

    // 5. ffh = rmsnorm(x1, n2) @ ff1_w + ff1_b       (fused A prep, bf16 out)
    gemm_fused<128, 2><<<dim3(FFN / 128, NTOK / 128), 256, SMSZ_P12_128>>>(
        p_x1, p_ff1T, ff1_b, nullptr, norm2_w, nullptr, p_ffh, FFN, 3);

    // 6. out = x1 + geglu(ffh) @ ff2_w + ff2_b       (fused A prep, fp32)
    gemm_fused<64, 3><<<dim3(CDIM / 64, NTOK / 128), 256, SMSZ_P3_64>>>(
        p_ffh, p_ff2T, ff2_b, p_x1, nullptr, out, nullptr, CDIM, 2);
}

// round 10
// speedup vs baseline: 1.7220x; 1.7220x over previous
#include <cuda_runtime.h>
#include <cuda_bf16.h>
#include <math.h>
#include <stdint.h>

// ---------------------------------------------------------------------------
// Problem constants (B=2, H=W=64, C=256, nh=4, hd=64, k=7)
// ---------------------------------------------------------------------------
#define NTOK   8192
#define CDIM   256
#define GK     256
#define QKVN   768
#define FFN    512
#define KS     7
#define KK     49

// ---------------------------------------------------------------------------
// Scratch (__device__ globals; allocation forbidden)
// ---------------------------------------------------------------------------
__device__ __nv_bfloat16 g_h   [NTOK * CDIM];
__device__ __nv_bfloat16 g_qkv [NTOK * QKVN];
__device__ __nv_bfloat16 g_attn[NTOK * CDIM];
__device__ float         g_x1  [NTOK * CDIM];
__device__ __nv_bfloat16 g_n2  [NTOK * CDIM];
__device__ __nv_bfloat16 g_ffh [NTOK * FFN];
__device__ __nv_bfloat16 g_g   [NTOK * CDIM];
__device__ __nv_bfloat16 g_wqkvT[QKVN * GK];
__device__ __nv_bfloat16 g_wprojT[CDIM * GK];
__device__ __nv_bfloat16 g_ff1T [FFN  * GK];
__device__ __nv_bfloat16 g_ff2T [CDIM * GK];

// ---------------------------------------------------------------------------
// PTX helpers
// ---------------------------------------------------------------------------
__device__ __forceinline__ uint32_t smem_u32(const void* p) {
    uint32_t a;
    asm("{ .reg .u64 t; cvta.to.shared.u64 t, %1; cvt.u32.u64 %0, t; }"
        : "=r"(a) : "l"(p));
    return a;
}
#define LDMATRIX_X4(r0, r1, r2, r3, a) \
    asm volatile("ldmatrix.sync.aligned.m8n8.x4.shared.b16 {%0,%1,%2,%3}, [%4];" \
                 : "=r"(r0), "=r"(r1), "=r"(r2), "=r"(r3) : "r"(a))
#define LDMATRIX_X4_TRANS(r0, r1, r2, r3, a) \
    asm volatile("ldmatrix.sync.aligned.m8n8.x4.trans.shared.b16 {%0,%1,%2,%3}, [%4];" \
                 : "=r"(r0), "=r"(r1), "=r"(r2), "=r"(r3) : "r"(a))
#define MMA_BF16(d, a, b) \
    asm volatile("mma.sync.aligned.m16n8k16.row.col.f32.bf16.bf16.f32 " \
                 "{%0,%1,%2,%3}, {%4,%5,%6,%7}, {%8,%9}, {%0,%1,%2,%3};" \
                 : "+f"((d)[0]), "+f"((d)[1]), "+f"((d)[2]), "+f"((d)[3]) \
                 : "r"((a)[0]), "r"((a)[1]), "r"((a)[2]), "r"((a)[3]), \
                   "r"((b)[0]), "r"((b)[1]))
#define CP_ASYNC16(dst, src) \
    asm volatile("cp.async.cg.shared.global [%0], [%1], 16;" :: "r"(dst), "l"(src))
#define CP_COMMIT() asm volatile("cp.async.commit_group;" ::: "memory")
#define CP_WAIT(n)  asm volatile("cp.async.wait_group %0;" :: "n"(n) : "memory")

__device__ __forceinline__ uint32_t swz(uint32_t off) { return off ^ ((off >> 3) & 0x70); }
__device__ __forceinline__ uint32_t packbf(float a, float b) {
    __nv_bfloat162 h = __floats2bfloat162_rn(a, b);
    return *reinterpret_cast<uint32_t*>(&h);
}

// ---------------------------------------------------------------------------
// Fused weight convert+transpose (one launch for all 4 weights)
// ---------------------------------------------------------------------------
__global__ void transpose_all_kernel(const float* __restrict__ w0, __nv_bfloat16* __restrict__ o0,
                                     const float* __restrict__ w1, __nv_bfloat16* __restrict__ o1,
                                     const float* __restrict__ w2, __nv_bfloat16* __restrict__ o2,
                                     const float* __restrict__ w3, __nv_bfloat16* __restrict__ o3)
{
    const float* w; __nv_bfloat16* o; int N, nb;
    const int bx = blockIdx.x;
    if      (bx < 24) { w = w0; o = o0; N = QKVN; nb = bx;      }
    else if (bx < 32) { w = w1; o = o1; N = CDIM; nb = bx - 24; }
    else if (bx < 48) { w = w2; o = o2; N = FFN;  nb = bx - 32; }
    else              { w = w3; o = o3; N = CDIM; nb = bx - 48; }

    __shared__ float t[32][33];
    const int n0 = nb * 32, k0 = blockIdx.y * 32;
    const int tx = threadIdx.x, ty = threadIdx.y;
    #pragma unroll
    for (int i = 0; i < 32; i += 8)
        t[ty + i][tx] = w[(size_t)(k0 + ty + i) * N + n0 + tx];
    __syncthreads();
    #pragma unroll
    for (int i = 0; i < 32; i += 8)
        o[(size_t)(n0 + ty + i) * GK + k0 + tx] = __float2bfloat16(t[tx][ty + i]);
}

// ---------------------------------------------------------------------------
// RMSNorm (+ optional RoPE2D), fp32 in, bf16 out.
// ---------------------------------------------------------------------------
__global__ void rmsnorm_rope_kernel(const float* __restrict__ x,
                                    const float* __restrict__ w,
                                    __nv_bfloat16* __restrict__ out,
                                    int do_rope)
{
    const int t = blockIdx.x;
    const int i = threadIdx.x;
    float2 v = reinterpret_cast<const float2*>(x + (size_t)t * CDIM)[i];

    float ss = v.x * v.x + v.y * v.y;
    #pragma unroll
    for (int off = 16; off; off >>= 1)
        ss += __shfl_xor_sync(0xffffffffu, ss, off);
    __shared__ float red[4];
    if ((i & 31) == 0) red[i >> 5] = ss;
    __syncthreads();
    const float r = rsqrtf((red[0] + red[1] + red[2] + red[3]) * (1.0f / CDIM) + 1e-6f);

    const float2 wv = reinterpret_cast<const float2*>(w)[i];
    float a = v.x * r * wv.x;
    float b = v.y * r * wv.y;

    if (do_rope) {
        const int yy = (t >> 6) & 63;
        const int xx = t & 63;
        const int j  = i & 63;
        const float pos = (i < 64) ? (float)yy : (float)xx;
        const float inv = exp2f((float)j * (-13.28771237954945f / 64.0f));
        float c, s;
        sincosf(pos * inv, &s, &c);
        const float na = a * c - b * s;
        const float nb = a * s + b * c;
        a = na; b = nb;
    }
    reinterpret_cast<__nv_bfloat162*>(out + (size_t)t * CDIM)[i] =
        __floats2bfloat162_rn(a, b);
}

// ---------------------------------------------------------------------------
// mma.sync bf16 GEMM: BM=64, BN=64, 128 threads (4 warps, 2Mx2N, warp 32x32),
// double-buffered K-chunk ring (2 x 16KB = 32KB) -> ~5 CTAs/SM.
// mode: 0 = bf16 out, 2 = fp32 +bias+residual, 3 = bf16 +bias
// ---------------------------------------------------------------------------
#define GS_STAGE 16384u           // 8KB A + 8KB B per stage
#define SM_SIZE  32768

__global__ __launch_bounds__(128, 5)
void gemm_mma_kernel(const __nv_bfloat16* __restrict__ A,
                     const __nv_bfloat16* __restrict__ Bt,
                     const float* __restrict__ bias,
                     const float* __restrict__ residual,
                     float* __restrict__ C,
                     __nv_bfloat16* __restrict__ Cb,
                     int N, int mode)
{
    extern __shared__ __align__(1024) char smem[];
    const uint32_t sb = smem_u32(smem);
    const int tid  = threadIdx.x;
    const int wid  = tid >> 5;
    const int lane = tid & 31;
    const int bm   = blockIdx.y * 64;
    const int bn   = blockIdx.x * 64;
    const int wm   = wid & 1;
    const int wn   = wid >> 1;

    const int lrow = tid >> 3;            // 0..15 (x4 iters -> 64 rows)
    const int lch  = tid & 7;

    #define LOAD_CHUNK(kc, stage) do {                                           \
        const uint32_t s0 = (uint32_t)(stage) * GS_STAGE;                        \
        _Pragma("unroll")                                                        \
        for (int it = 0; it < 4; it++) {                                         \
            const int row = it * 16 + lrow;                                      \
            uint32_t off = swz((uint32_t)row * 128u + (uint32_t)lch * 16u);      \
            CP_ASYNC16(sb + s0 + off,                                            \
                       A  + (size_t)(bm + row) * GK + (kc) * 64 + lch * 8);      \
            CP_ASYNC16(sb + s0 + 8192u + off,                                    \
                       Bt + (size_t)(bn + row) * GK + (kc) * 64 + lch * 8);      \
        }                                                                        \
        CP_COMMIT();                                                             \
    } while (0)

    LOAD_CHUNK(0, 0);
    LOAD_CHUNK(1, 1);

    float acc[2][4][4] = {};
    const int mtx = lane >> 3;
    const int l7  = lane & 7;

    #pragma unroll
    for (int kc = 0; kc < 4; kc++) {
        if (kc < 3) CP_WAIT(1); else CP_WAIT(0);
        __syncthreads();

        const uint32_t sA = sb + (uint32_t)(kc & 1) * GS_STAGE;
        const uint32_t sB = sA + 8192u;

        #pragma unroll
        for (int s16 = 0; s16 < 4; s16++) {
            const int chunk0 = s16 * 2;

            uint32_t af[2][4];
            #pragma unroll
            for (int mt = 0; mt < 2; mt++) {
                const int row   = wm * 32 + mt * 16 + (mtx & 1) * 8 + l7;
                const int chunk = chunk0 + (mtx >> 1);
                LDMATRIX_X4(af[mt][0], af[mt][1], af[mt][2], af[mt][3],
                            sA + swz((uint32_t)row * 128u + (uint32_t)chunk * 16u));
            }
            uint32_t bf[4][2];
            #pragma unroll
            for (int pair = 0; pair < 2; pair++) {
                const int nrow  = wn * 32 + pair * 16 + (mtx >> 1) * 8 + l7;
                const int chunk = chunk0 + (mtx & 1);
                LDMATRIX_X4(bf[pair * 2][0], bf[pair * 2][1],
                            bf[pair * 2 + 1][0], bf[pair * 2 + 1][1],
                            sB + swz((uint32_t)nrow * 128u + (uint32_t)chunk * 16u));
            }
            #pragma unroll
            for (int mt = 0; mt < 2; mt++)
                #pragma unroll
                for (int nt = 0; nt < 4; nt++)
                    MMA_BF16(acc[mt][nt], af[mt], bf[nt]);
        }
        __syncthreads();
        if (kc < 2) LOAD_CHUNK(kc + 2, kc & 1);
    }
    #undef LOAD_CHUNK

    const int rbase = bm + wm * 32 + (lane >> 2);
    const int cbase = bn + wn * 32 + (lane & 3) * 2;
    #pragma unroll
    for (int mt = 0; mt < 2; mt++) {
        #pragma unroll
        for (int half = 0; half < 2; half++) {
            const int row = rbase + mt * 16 + half * 8;
            #pragma unroll
            for (int nt = 0; nt < 4; nt++) {
                const int col = cbase + nt * 8;
                float ox = acc[mt][nt][half * 2];
                float oy = acc[mt][nt][half * 2 + 1];
                const size_t idx = (size_t)row * N + col;
                if (mode == 0) {
                    *reinterpret_cast<__nv_bfloat162*>(&Cb[idx]) =
                        __floats2bfloat162_rn(ox, oy);
                } else {
                    ox += bias[col];
                    oy += bias[col + 1];
                    if (mode == 2) {
                        const float2 rr = *reinterpret_cast<const float2*>(&residual[idx]);
                        ox += rr.x; oy += rr.y;
                        *reinterpret_cast<float2*>(&C[idx]) = make_float2(ox, oy);
                    } else {   // mode == 3
                        *reinterpret_cast<__nv_bfloat162*>(&Cb[idx]) =
                            __floats2bfloat162_rn(ox, oy);
                    }
                }
            }
        }
    }
}

// ---------------------------------------------------------------------------
// Tiled tensor-core neighborhood attention (unchanged from R8).
// ---------------------------------------------------------------------------
#define AT_Q    0
#define AT_K    8192
#define AT_V    36864
#define AT_RED  8192
#define AT_MAX  65536
#define AT_SUM  66048
#define AT_SIZE 66560
#define REDW    68

__global__ __launch_bounds__(256, 2)
void attn_mma_kernel(const __nv_bfloat16* __restrict__ qkv,
                     __nv_bfloat16* __restrict__ out)
{
    extern __shared__ __align__(1024) char smem[];
    const uint32_t sb = smem_u32(smem);
    float* smax = reinterpret_cast<float*>(smem + AT_MAX);
    float* ssum = reinterpret_cast<float*>(smem + AT_SUM);
    float* sred = reinterpret_cast<float*>(smem + AT_RED);

    const int tid  = threadIdx.x;
    const int wid  = tid >> 5;
    const int lane = tid & 31;
    const int head = blockIdx.y;
    const int b    = blockIdx.z;
    const int ty0  = (blockIdx.x >> 3) * 8;
    const int tx0  = (blockIdx.x & 7) * 8;
    const int ny0  = min(max(ty0 - 3, 0), 50);
    const int nx0  = min(max(tx0 - 3, 0), 50);

    const __nv_bfloat16* base = qkv + (size_t)b * 4096 * QKVN + head * 64;

    #pragma unroll
    for (int i = 0; i < 2; i++) {
        const int idx = i * 256 + tid;
        const int m = idx >> 3, ch = idx & 7;
        const int y = ty0 + (m >> 3), x = tx0 + (m & 7);
        uint32_t off = swz((uint32_t)m * 128u + (uint32_t)ch * 16u);
        CP_ASYNC16(sb + AT_Q + off, base + (size_t)(y * 64 + x) * QKVN + ch * 8);
    }
    CP_COMMIT();
    #pragma unroll
    for (int i = 0; i < 7; i++) {
        const int idx = i * 256 + tid;
        const int kv = idx >> 3, ch = idx & 7;
        const int r = kv >> 4, c = kv & 15;
        uint32_t off = swz((uint32_t)kv * 128u + (uint32_t)ch * 16u);
        if (c < 14)
            CP_ASYNC16(sb + AT_K + off,
                       base + (size_t)((ny0 + r) * 64 + nx0 + c) * QKVN + CDIM + ch * 8);
        else
            *reinterpret_cast<uint4*>(smem + AT_K + off) = make_uint4(0, 0, 0, 0);
    }
    CP_COMMIT();
    #pragma unroll
    for (int i = 0; i < 7; i++) {
        const int idx = i * 256 + tid;
        const int kv = idx >> 3, ch = idx & 7;
        const int r = kv >> 4, c = kv & 15;
        uint32_t off = swz((uint32_t)kv * 128u + (uint32_t)ch * 16u);
        if (c < 14)
            CP_ASYNC16(sb + AT_V + off,
                       base + (size_t)((ny0 + r) * 64 + nx0 + c) * QKVN + 2 * CDIM + ch * 8);
        else
            *reinterpret_cast<uint4*>(smem + AT_V + off) = make_uint4(0, 0, 0, 0);
    }
    CP_COMMIT();

    const int wm  = wid & 3;
    const int wn  = wid >> 2;
    const int mtx = lane >> 3;
    const int l7  = lane & 7;

    CP_WAIT(1);
    __syncthreads();

    uint32_t af[4][4];
    #pragma unroll
    for (int k16 = 0; k16 < 4; k16++) {
        const int row   = wm * 16 + (mtx & 1) * 8 + l7;
        const int chunk = k16 * 2 + (mtx >> 1);
        LDMATRIX_X4(af[k16][0], af[k16][1], af[k16][2], af[k16][3],
                    sb + AT_Q + swz((uint32_t)row * 128u + (uint32_t)chunk * 16u));
    }

    float acc[14][4] = {};
    #pragma unroll
    for (int k16 = 0; k16 < 4; k16++) {
        #pragma unroll
        for (int grp = 0; grp < 2; grp++) {
            const int nt0    = grp * 8;
            const int npairs = grp ? 3 : 4;
            uint32_t bf[8][2];
            #pragma unroll
            for (int pair = 0; pair < 4; pair++) {
                if (pair < npairs) {
                    const int nrow  = wn * 112 + (nt0 + pair * 2) * 8 + (mtx >> 1) * 8 + l7;
                    const int chunk = k16 * 2 + (mtx & 1);
                    LDMATRIX_X4(bf[pair * 2][0], bf[pair * 2][1],
                                bf[pair * 2 + 1][0], bf[pair * 2 + 1][1],
                                sb + AT_K + swz((uint32_t)nrow * 128u + (uint32_t)chunk * 16u));
                }
            }
            const int ntiles = grp ? 6 : 8;
            #pragma unroll
            for (int j = 0; j < 8; j++)
                if (j < ntiles)
                    MMA_BF16(acc[nt0 + j], af[k16], bf[j]);
        }
    }

    const int row0 = wm * 16 + (lane >> 2);
    const int row1 = row0 + 8;
    const int y_a = ty0 + (row0 >> 3), x_a = tx0 + (row0 & 7);
    const int y_b = ty0 + (row1 >> 3), x_b = tx0 + (row1 & 7);
    const int rlo_a = min(max(y_a - 3, 0), 57) - ny0;
    const int clo_a = min(max(x_a - 3, 0), 57) - nx0;
    const int rlo_b = min(max(y_b - 3, 0), 57) - ny0;
    const int clo_b = min(max(x_b - 3, 0), 57) - nx0;

    uint32_t vm_a = 0, vm_b = 0;
    #pragma unroll
    for (int nt = 0; nt < 14; nt++) {
        #pragma unroll
        for (int j = 0; j < 2; j++) {
            const int n = wn * 112 + nt * 8 + (lane & 3) * 2 + j;
            const int r = n >> 4, c = n & 15;
            if (c < 14 && (unsigned)(r - rlo_a) < 7u && (unsigned)(c - clo_a) < 7u)
                vm_a |= 1u << (nt * 2 + j);
            if (c < 14 && (unsigned)(r - rlo_b) < 7u && (unsigned)(c - clo_b) < 7u)
                vm_b |= 1u << (nt * 2 + j);
        }
    }

    float mx_a = -3e38f, mx_b = -3e38f;
    #pragma unroll
    for (int nt = 0; nt < 14; nt++) {
        #pragma unroll
        for (int j = 0; j < 2; j++) {
            if (vm_a & (1u << (nt * 2 + j))) mx_a = fmaxf(mx_a, acc[nt][j]);
            if (vm_b & (1u << (nt * 2 + j))) mx_b = fmaxf(mx_b, acc[nt][2 + j]);
        }
    }
    mx_a = fmaxf(mx_a, __shfl_xor_sync(0xffffffffu, mx_a, 1));
    mx_a = fmaxf(mx_a, __shfl_xor_sync(0xffffffffu, mx_a, 2));
    mx_b = fmaxf(mx_b, __shfl_xor_sync(0xffffffffu, mx_b, 1));
    mx_b = fmaxf(mx_b, __shfl_xor_sync(0xffffffffu, mx_b, 2));
    if ((lane & 3) == 0) {
        smax[row0 * 2 + wn] = mx_a;
        smax[row1 * 2 + wn] = mx_b;
    }
    __syncthreads();
    const float M_a = fmaxf(smax[row0 * 2], smax[row0 * 2 + 1]);
    const float M_b = fmaxf(smax[row1 * 2], smax[row1 * 2 + 1]);

    const float SC = 0.18033688011112042f;
    float sm_a = 0.0f, sm_b = 0.0f;
    #pragma unroll
    for (int nt = 0; nt < 14; nt++) {
        #pragma unroll
        for (int j = 0; j < 2; j++) {
            float ea = (vm_a & (1u << (nt * 2 + j)))
                     ? exp2f((acc[nt][j] - M_a) * SC) : 0.0f;
            float eb = (vm_b & (1u << (nt * 2 + j)))
                     ? exp2f((acc[nt][2 + j] - M_b) * SC) : 0.0f;
            acc[nt][j] = ea; acc[nt][2 + j] = eb;
            sm_a += ea; sm_b += eb;
        }
    }
    sm_a += __shfl_xor_sync(0xffffffffu, sm_a, 1);
    sm_a += __shfl_xor_sync(0xffffffffu, sm_a, 2);
    sm_b += __shfl_xor_sync(0xffffffffu, sm_b, 1);
    sm_b += __shfl_xor_sync(0xffffffffu, sm_b, 2);
    if ((lane & 3) == 0) {
        ssum[row0 * 2 + wn] = sm_a;
        ssum[row1 * 2 + wn] = sm_b;
    }

    uint32_t pf[7][4];
    #pragma unroll
    for (int s = 0; s < 7; s++) {
        pf[s][0] = packbf(acc[2 * s][0],     acc[2 * s][1]);
        pf[s][1] = packbf(acc[2 * s][2],     acc[2 * s][3]);
        pf[s][2] = packbf(acc[2 * s + 1][0], acc[2 * s + 1][1]);
        pf[s][3] = packbf(acc[2 * s + 1][2], acc[2 * s + 1][3]);
    }

    CP_WAIT(0);
    __syncthreads();

    float accO[8][4] = {};
    #pragma unroll
    for (int s = 0; s < 7; s++) {
        uint32_t vf[8][2];
        #pragma unroll
        for (int g2 = 0; g2 < 4; g2++) {
            const int kvrow = (wn * 7 + s) * 16 + (lane & 15);
            const int colb  = (g2 * 16 + (lane >> 4) * 8) * 2;
            LDMATRIX_X4_TRANS(vf[g2 * 2][0], vf[g2 * 2][1],
                              vf[g2 * 2 + 1][0], vf[g2 * 2 + 1][1],
                              sb + AT_V + swz((uint32_t)kvrow * 128u + (uint32_t)colb));
        }
        #pragma unroll
        for (int nt = 0; nt < 8; nt++)
            MMA_BF16(accO[nt], pf[s], vf[nt]);
    }

    if (wn == 1) {
        #pragma unroll
        for (int nt = 0; nt < 8; nt++) {
            const int col = nt * 8 + (lane & 3) * 2;
            *reinterpret_cast<float2*>(&sred[row0 * REDW + col]) =
                make_float2(accO[nt][0], accO[nt][1]);
            *reinterpret_cast<float2*>(&sred[row1 * REDW + col]) =
                make_float2(accO[nt][2], accO[nt][3]);
        }
    }
    __syncthreads();

    if (wn == 0) {
        const float inv_a = 1.0f / (ssum[row0 * 2] + ssum[row0 * 2 + 1]);
        const float inv_b = 1.0f / (ssum[row1 * 2] + ssum[row1 * 2 + 1]);
        const size_t t_a = (size_t)b * 4096 + (size_t)(y_a * 64 + x_a);
        const size_t t_b = (size_t)b * 4096 + (size_t)(y_b * 64 + x_b);
        #pragma unroll
        for (int nt = 0; nt < 8; nt++) {
            const int col = nt * 8 + (lane & 3) * 2;
            const float2 ra = *reinterpret_cast<const float2*>(&sred[row0 * REDW + col]);
            const float2 rb = *reinterpret_cast<const float2*>(&sred[row1 * REDW + col]);
            *reinterpret_cast<__nv_bfloat162*>(out + t_a * CDIM + head * 64 + col) =
                __floats2bfloat162_rn((accO[nt][0] + ra.x) * inv_a,
                                      (accO[nt][1] + ra.y) * inv_a);
            *reinterpret_cast<__nv_bfloat162*>(out + t_b * CDIM + head * 64 + col) =
                __floats2bfloat162_rn((accO[nt][2] + rb.x) * inv_b,
                                      (accO[nt][3] + rb.y) * inv_b);
        }
    }
}

// ---------------------------------------------------------------------------
// GeGLU: g = gelu_exact(gate) * value   (bf16 in, bf16 out)
// ---------------------------------------------------------------------------
__global__ void geglu_kernel(const __nv_bfloat16* __restrict__ ffh,
                             __nv_bfloat16* __restrict__ g)
{
    const int idx = blockIdx.x * blockDim.x + threadIdx.x;
    const int row = idx >> 8;
    const int col = idx & 255;
    const float gate = __bfloat162float(ffh[(size_t)row * FFN + col]);
    const float val  = __bfloat162float(ffh[(size_t)row * FFN + CDIM + col]);
    const float ge = 0.5f * gate * (1.0f + erff(gate * 0.70710678118654752f));
    g[idx] = __float2bfloat16(ge * val);
}

// ---------------------------------------------------------------------------
// Launch
// ---------------------------------------------------------------------------
extern "C" void kernel_launch(void* const* d_in, const int* in_sizes, int n_in,
                              void* d_out, int out_size)
{
    const float* x       = (const float*)d_in[0];
    const float* norm1_w = (const float*)d_in[1];
    const float* norm2_w = (const float*)d_in[2];
    const float* w_qkv   = (const float*)d_in[3];
    const float* w_proj  = (const float*)d_in[4];
    const float* b_proj  = (const float*)d_in[5];
    const float* ff1_w   = (const float*)d_in[6];
    const float* ff1_b   = (const float*)d_in[7];
    const float* ff2_w   = (const float*)d_in[8];
    const float* ff2_b   = (const float*)d_in[9];
    float* out = (float*)d_out;

    __nv_bfloat16 *p_h, *p_qkv, *p_attn, *p_n2, *p_g, *p_ffh;
    __nv_bfloat16 *p_wqkvT, *p_wprojT, *p_ff1T, *p_ff2T;
    float *p_x1;
    cudaGetSymbolAddress((void**)&p_h,      g_h);
    cudaGetSymbolAddress((void**)&p_qkv,    g_qkv);
    cudaGetSymbolAddress((void**)&p_attn,   g_attn);
    cudaGetSymbolAddress((void**)&p_x1,     g_x1);
    cudaGetSymbolAddress((void**)&p_n2,     g_n2);
    cudaGetSymbolAddress((void**)&p_ffh,    g_ffh);
    cudaGetSymbolAddress((void**)&p_g,      g_g);
    cudaGetSymbolAddress((void**)&p_wqkvT,  g_wqkvT);
    cudaGetSymbolAddress((void**)&p_wprojT, g_wprojT);
    cudaGetSymbolAddress((void**)&p_ff1T,   g_ff1T);
    cudaGetSymbolAddress((void**)&p_ff2T,   g_ff2T);

    cudaFuncSetAttribute(gemm_mma_kernel,
                         cudaFuncAttributeMaxDynamicSharedMemorySize, SM_SIZE);
    cudaFuncSetAttribute(attn_mma_kernel,
                         cudaFuncAttributeMaxDynamicSharedMemorySize, AT_SIZE);

    // 0. all weight transposes in one launch
    transpose_all_kernel<<<dim3(56, 8), dim3(32, 8)>>>(
        w_qkv, p_wqkvT, w_proj, p_wprojT, ff1_w, p_ff1T, ff2_w, p_ff2T);

    // 1. h = rope2d(rmsnorm(x)) -> bf16
    rmsnorm_rope_kernel<<<NTOK, 128>>>(x, norm1_w, p_h, 1);

    // 2. qkv = h @ w_qkv -> bf16              (1536 CTAs)
    gemm_mma_kernel<<<dim3(QKVN / 64, NTOK / 64), 128, SM_SIZE>>>(
        p_h, p_wqkvT, nullptr, nullptr, nullptr, p_qkv, QKVN, 0);

    // 3. attention -> bf16
    attn_mma_kernel<<<dim3(64, 4, 2), 256, AT_SIZE>>>(p_qkv, p_attn);

    // 4. x1 = x + attn @ w_proj + b_proj      (fp32, 512 CTAs)
    gemm_mma_kernel<<<dim3(CDIM / 64, NTOK / 64), 128, SM_SIZE>>>(
        p_attn, p_wprojT, b_proj, x, p_x1, nullptr, CDIM, 2);

    // 5. n2 = rmsnorm(x1) -> bf16
    rmsnorm_rope_kernel<<<NTOK, 128>>>(p_x1, norm2_w, p_n2, 0);

    // 6. ffh = n2 @ ff1_w + ff1_b -> bf16     (1024 CTAs)
    gemm_mma_kernel<<<dim3(FFN / 64, NTOK / 64), 128, SM_SIZE>>>(
        p_n2, p_ff1T, ff1_b, nullptr, nullptr, p_ffh, FFN, 3);

    // 7. g = gelu(gate) * value -> bf16
    geglu_kernel<<<(NTOK * CDIM) / 256, 256>>>(p_ffh, p_g);

    // 8. out = x1 + g @ ff2_w + ff2_b         (fp32, 512 CTAs)
    gemm_mma_kernel<<<dim3(CDIM / 64, NTOK / 64), 128, SM_SIZE>>>(
        p_g, p_ff2T, ff2_b, p_x1, out, nullptr, CDIM, 2);
}

// round 11
// speedup vs baseline: 1.8800x; 1.0917x over previous
#include <cuda_runtime.h>
#include <cuda_bf16.h>
#include <math.h>
#include <stdint.h>

// ---------------------------------------------------------------------------
// Problem constants (B=2, H=W=64, C=256, nh=4, hd=64, k=7)
// ---------------------------------------------------------------------------
#define NTOK   8192
#define CDIM   256
#define GK     256
#define QKVN   768
#define FFN    512
#define KS     7
#define KK     49

// ---------------------------------------------------------------------------
// Scratch (__device__ globals; allocation forbidden)
// ---------------------------------------------------------------------------
__device__ __nv_bfloat16 g_h   [NTOK * CDIM];
__device__ __nv_bfloat16 g_qkv [NTOK * QKVN];
__device__ __nv_bfloat16 g_attn[NTOK * CDIM];
__device__ float         g_x1  [NTOK * CDIM];
__device__ __nv_bfloat16 g_n2  [NTOK * CDIM];
__device__ __nv_bfloat16 g_g   [NTOK * CDIM];
__device__ __nv_bfloat16 g_wqkvT[QKVN * GK];
__device__ __nv_bfloat16 g_wprojT[CDIM * GK];
__device__ __nv_bfloat16 g_ff1T [FFN  * GK];   // PERMUTED column order
__device__ __nv_bfloat16 g_ff2T [CDIM * GK];

// ---------------------------------------------------------------------------
// PTX helpers
// ---------------------------------------------------------------------------
__device__ __forceinline__ uint32_t smem_u32(const void* p) {
    uint32_t a;
    asm("{ .reg .u64 t; cvta.to.shared.u64 t, %1; cvt.u32.u64 %0, t; }"
        : "=r"(a) : "l"(p));
    return a;
}
#define LDMATRIX_X4(r0, r1, r2, r3, a) \
    asm volatile("ldmatrix.sync.aligned.m8n8.x4.shared.b16 {%0,%1,%2,%3}, [%4];" \
                 : "=r"(r0), "=r"(r1), "=r"(r2), "=r"(r3) : "r"(a))
#define LDMATRIX_X4_TRANS(r0, r1, r2, r3, a) \
    asm volatile("ldmatrix.sync.aligned.m8n8.x4.trans.shared.b16 {%0,%1,%2,%3}, [%4];" \
                 : "=r"(r0), "=r"(r1), "=r"(r2), "=r"(r3) : "r"(a))
#define MMA_BF16(d, a, b) \
    asm volatile("mma.sync.aligned.m16n8k16.row.col.f32.bf16.bf16.f32 " \
                 "{%0,%1,%2,%3}, {%4,%5,%6,%7}, {%8,%9}, {%0,%1,%2,%3};" \
                 : "+f"((d)[0]), "+f"((d)[1]), "+f"((d)[2]), "+f"((d)[3]) \
                 : "r"((a)[0]), "r"((a)[1]), "r"((a)[2]), "r"((a)[3]), \
                   "r"((b)[0]), "r"((b)[1]))
#define CP_ASYNC16(dst, src) \
    asm volatile("cp.async.cg.shared.global [%0], [%1], 16;" :: "r"(dst), "l"(src))
#define CP_COMMIT() asm volatile("cp.async.commit_group;" ::: "memory")
#define CP_WAIT(n)  asm volatile("cp.async.wait_group %0;" :: "n"(n) : "memory")

__device__ __forceinline__ uint32_t swz(uint32_t off) { return off ^ ((off >> 3) & 0x70); }
__device__ __forceinline__ uint32_t packbf(float a, float b) {
    __nv_bfloat162 h = __floats2bfloat162_rn(a, b);
    return *reinterpret_cast<uint32_t*>(&h);
}
// ff1 permutation: out col n -> source col of ff1_w
__device__ __forceinline__ int ff1_src(int n) {
    const int within = n & 127, blk = n >> 7;
    return (within < 64) ? (blk * 64 + within) : (256 + blk * 64 + within - 64);
}

// ---------------------------------------------------------------------------
// Fused weight convert+transpose. ff1 (bx 32..47) gets PERMUTED column order.
// ---------------------------------------------------------------------------
__global__ void transpose_all_kernel(const float* __restrict__ w0, __nv_bfloat16* __restrict__ o0,
                                     const float* __restrict__ w1, __nv_bfloat16* __restrict__ o1,
                                     const float* __restrict__ w2, __nv_bfloat16* __restrict__ o2,
                                     const float* __restrict__ w3, __nv_bfloat16* __restrict__ o3)
{
    const float* w; __nv_bfloat16* o; int N, nb; bool perm = false;
    const int bx = blockIdx.x;
    if      (bx < 24) { w = w0; o = o0; N = QKVN; nb = bx;      }
    else if (bx < 32) { w = w1; o = o1; N = CDIM; nb = bx - 24; }
    else if (bx < 48) { w = w2; o = o2; N = FFN;  nb = bx - 32; perm = true; }
    else              { w = w3; o = o3; N = CDIM; nb = bx - 48; }

    __shared__ float t[32][33];
    const int n0 = nb * 32, k0 = blockIdx.y * 32;
    // 32-aligned blocks stay inside one 64-wide gate/value piece -> contiguous src
    const int s0 = perm ? ff1_src(n0) : n0;
    const int tx = threadIdx.x, ty = threadIdx.y;
    #pragma unroll
    for (int i = 0; i < 32; i += 8)
        t[ty + i][tx] = w[(size_t)(k0 + ty + i) * N + s0 + tx];
    __syncthreads();
    #pragma unroll
    for (int i = 0; i < 32; i += 8)
        o[(size_t)(n0 + ty + i) * GK + k0 + tx] = __float2bfloat16(t[tx][ty + i]);
}

// ---------------------------------------------------------------------------
// RMSNorm + RoPE2D, fp32 in, bf16 out.
// ---------------------------------------------------------------------------
__global__ void rmsnorm_rope_kernel(const float* __restrict__ x,
                                    const float* __restrict__ w,
                                    __nv_bfloat16* __restrict__ out)
{
    const int t = blockIdx.x;
    const int i = threadIdx.x;
    float2 v = reinterpret_cast<const float2*>(x + (size_t)t * CDIM)[i];

    float ss = v.x * v.x + v.y * v.y;
    #pragma unroll
    for (int off = 16; off; off >>= 1)
        ss += __shfl_xor_sync(0xffffffffu, ss, off);
    __shared__ float red[4];
    if ((i & 31) == 0) red[i >> 5] = ss;
    __syncthreads();
    const float r = rsqrtf((red[0] + red[1] + red[2] + red[3]) * (1.0f / CDIM) + 1e-6f);

    const float2 wv = reinterpret_cast<const float2*>(w)[i];
    float a = v.x * r * wv.x;
    float b = v.y * r * wv.y;

    const int yy = (t >> 6) & 63;
    const int xx = t & 63;
    const int j  = i & 63;
    const float pos = (i < 64) ? (float)yy : (float)xx;
    const float inv = exp2f((float)j * (-13.28771237954945f / 64.0f));
    float c, s;
    sincosf(pos * inv, &s, &c);
    reinterpret_cast<__nv_bfloat162*>(out + (size_t)t * CDIM)[i] =
        __floats2bfloat162_rn(a * c - b * s, a * s + b * c);
}

// ---------------------------------------------------------------------------
// Generic mma.sync bf16 GEMM (R10): BM=64, BN=64, 128 threads, ring 32KB.
// mode: 0 = bf16 out, 2 = fp32 +bias+residual
// ---------------------------------------------------------------------------
#define GS_STAGE 16384u
#define SM_SIZE  32768

__global__ __launch_bounds__(128, 5)
void gemm_mma_kernel(const __nv_bfloat16* __restrict__ A,
                     const __nv_bfloat16* __restrict__ Bt,
                     const float* __restrict__ bias,
                     const float* __restrict__ residual,
                     float* __restrict__ C,
                     __nv_bfloat16* __restrict__ Cb,
                     int N, int mode)
{
    extern __shared__ __align__(1024) char smem[];
    const uint32_t sb = smem_u32(smem);
    const int tid  = threadIdx.x;
    const int wid  = tid >> 5;
    const int lane = tid & 31;
    const int bm   = blockIdx.y * 64;
    const int bn   = blockIdx.x * 64;
    const int wm   = wid & 1;
    const int wn   = wid >> 1;
    const int lrow = tid >> 3;
    const int lch  = tid & 7;

    #define LOAD_CHUNK(kc, stage) do {                                           \
        const uint32_t s0 = (uint32_t)(stage) * GS_STAGE;                        \
        _Pragma("unroll")                                                        \
        for (int it = 0; it < 4; it++) {                                         \
            const int row = it * 16 + lrow;                                      \
            uint32_t off = swz((uint32_t)row * 128u + (uint32_t)lch * 16u);      \
            CP_ASYNC16(sb + s0 + off,                                            \
                       A  + (size_t)(bm + row) * GK + (kc) * 64 + lch * 8);      \
            CP_ASYNC16(sb + s0 + 8192u + off,                                    \
                       Bt + (size_t)(bn + row) * GK + (kc) * 64 + lch * 8);      \
        }                                                                        \
        CP_COMMIT();                                                             \
    } while (0)

    LOAD_CHUNK(0, 0);
    LOAD_CHUNK(1, 1);

    float acc[2][4][4] = {};
    const int mtx = lane >> 3;
    const int l7  = lane & 7;

    #pragma unroll
    for (int kc = 0; kc < 4; kc++) {
        if (kc < 3) CP_WAIT(1); else CP_WAIT(0);
        __syncthreads();
        const uint32_t sA = sb + (uint32_t)(kc & 1) * GS_STAGE;
        const uint32_t sB = sA + 8192u;

        #pragma unroll
        for (int s16 = 0; s16 < 4; s16++) {
            const int chunk0 = s16 * 2;
            uint32_t af[2][4];
            #pragma unroll
            for (int mt = 0; mt < 2; mt++) {
                const int row   = wm * 32 + mt * 16 + (mtx & 1) * 8 + l7;
                const int chunk = chunk0 + (mtx >> 1);
                LDMATRIX_X4(af[mt][0], af[mt][1], af[mt][2], af[mt][3],
                            sA + swz((uint32_t)row * 128u + (uint32_t)chunk * 16u));
            }
            uint32_t bf[4][2];
            #pragma unroll
            for (int pair = 0; pair < 2; pair++) {
                const int nrow  = wn * 32 + pair * 16 + (mtx >> 1) * 8 + l7;
                const int chunk = chunk0 + (mtx & 1);
                LDMATRIX_X4(bf[pair * 2][0], bf[pair * 2][1],
                            bf[pair * 2 + 1][0], bf[pair * 2 + 1][1],
                            sB + swz((uint32_t)nrow * 128u + (uint32_t)chunk * 16u));
            }
            #pragma unroll
            for (int mt = 0; mt < 2; mt++)
                #pragma unroll
                for (int nt = 0; nt < 4; nt++)
                    MMA_BF16(acc[mt][nt], af[mt], bf[nt]);
        }
        __syncthreads();
        if (kc < 2) LOAD_CHUNK(kc + 2, kc & 1);
    }
    #undef LOAD_CHUNK

    const int rbase = bm + wm * 32 + (lane >> 2);
    const int cbase = bn + wn * 32 + (lane & 3) * 2;
    #pragma unroll
    for (int mt = 0; mt < 2; mt++) {
        #pragma unroll
        for (int half = 0; half < 2; half++) {
            const int row = rbase + mt * 16 + half * 8;
            #pragma unroll
            for (int nt = 0; nt < 4; nt++) {
                const int col = cbase + nt * 8;
                float ox = acc[mt][nt][half * 2];
                float oy = acc[mt][nt][half * 2 + 1];
                const size_t idx = (size_t)row * N + col;
                if (mode == 0) {
                    *reinterpret_cast<__nv_bfloat162*>(&Cb[idx]) =
                        __floats2bfloat162_rn(ox, oy);
                } else {
                    ox += bias[col];
                    oy += bias[col + 1];
                    const float2 rr = *reinterpret_cast<const float2*>(&residual[idx]);
                    *reinterpret_cast<float2*>(&C[idx]) =
                        make_float2(ox + rr.x, oy + rr.y);
                }
            }
        }
    }
}

// ---------------------------------------------------------------------------
// proj GEMM + residual + fused RMSNorm2 epilogue.
// BM=64, BN=256 (full width), 256 threads (8 warps: 2M x 4N, warp 32x64).
// Writes x1 (fp32) and n2 (bf16).
// ---------------------------------------------------------------------------
#define PJ_STG  40960u            // 8KB A + 32KB B per stage
#define PJ_SIZE 81920

__global__ __launch_bounds__(256, 2)
void proj_norm_kernel(const __nv_bfloat16* __restrict__ A,
                      const __nv_bfloat16* __restrict__ Bt,
                      const float* __restrict__ bias,
                      const float* __restrict__ residual,
                      const float* __restrict__ n2w,
                      float* __restrict__ X1,
                      __nv_bfloat16* __restrict__ N2)
{
    extern __shared__ __align__(1024) char smem[];
    const uint32_t sb = smem_u32(smem);
    float* sredn = reinterpret_cast<float*>(smem);    // [64][4] (stage0, dead)
    const int tid  = threadIdx.x;
    const int wid  = tid >> 5;
    const int lane = tid & 31;
    const int bm   = blockIdx.x * 64;
    const int wm   = wid & 1;
    const int wn   = wid >> 1;                        // 0..3, 64 cols each
    const int lrow = tid >> 3;                        // 0..31
    const int lch  = tid & 7;

    #define PJ_LOAD(kc, stage) do {                                              \
        const uint32_t s0 = (uint32_t)(stage) * PJ_STG;                          \
        _Pragma("unroll")                                                        \
        for (int it = 0; it < 2; it++) {                                         \
            const int row = it * 32 + lrow;                                      \
            uint32_t off = swz((uint32_t)row * 128u + (uint32_t)lch * 16u);      \
            CP_ASYNC16(sb + s0 + off,                                            \
                       A + (size_t)(bm + row) * GK + (kc) * 64 + lch * 8);       \
        }                                                                        \
        _Pragma("unroll")                                                        \
        for (int it = 0; it < 8; it++) {                                         \
            const int row = it * 32 + lrow;                                      \
            uint32_t off = swz((uint32_t)row * 128u + (uint32_t)lch * 16u);      \
            CP_ASYNC16(sb + s0 + 8192u + off,                                    \
                       Bt + (size_t)row * GK + (kc) * 64 + lch * 8);             \
        }                                                                        \
        CP_COMMIT();                                                             \
    } while (0)

    PJ_LOAD(0, 0);
    PJ_LOAD(1, 1);

    float acc[2][8][4] = {};
    const int mtx = lane >> 3;
    const int l7  = lane & 7;

    #pragma unroll
    for (int kc = 0; kc < 4; kc++) {
        if (kc < 3) CP_WAIT(1); else CP_WAIT(0);
        __syncthreads();
        const uint32_t sA = sb + (uint32_t)(kc & 1) * PJ_STG;
        const uint32_t sB = sA + 8192u;

        #pragma unroll
        for (int s16 = 0; s16 < 4; s16++) {
            const int chunk0 = s16 * 2;
            uint32_t af[2][4];
            #pragma unroll
            for (int mt = 0; mt < 2; mt++) {
                const int row   = wm * 32 + mt * 16 + (mtx & 1) * 8 + l7;
                const int chunk = chunk0 + (mtx >> 1);
                LDMATRIX_X4(af[mt][0], af[mt][1], af[mt][2], af[mt][3],
                            sA + swz((uint32_t)row * 128u + (uint32_t)chunk * 16u));
            }
            uint32_t bf[8][2];
            #pragma unroll
            for (int pair = 0; pair < 4; pair++) {
                const int nrow  = wn * 64 + pair * 16 + (mtx >> 1) * 8 + l7;
                const int chunk = chunk0 + (mtx & 1);
                LDMATRIX_X4(bf[pair * 2][0], bf[pair * 2][1],
                            bf[pair * 2 + 1][0], bf[pair * 2 + 1][1],
                            sB + swz((uint32_t)nrow * 128u + (uint32_t)chunk * 16u));
            }
            #pragma unroll
            for (int mt = 0; mt < 2; mt++)
                #pragma unroll
                for (int nt = 0; nt < 8; nt++)
                    MMA_BF16(acc[mt][nt], af[mt], bf[nt]);
        }
        __syncthreads();
        if (kc < 2) PJ_LOAD(kc + 2, kc & 1);
    }
    #undef PJ_LOAD

    // ---- epilogue: bias+residual -> x1; rowwise sumsq -> rmsnorm -> n2 ----
    const int rl   = wm * 32 + (lane >> 2);     // local row base
    const int cbse = wn * 64 + (lane & 3) * 2;
    float ss[2][2] = {};
    #pragma unroll
    for (int mt = 0; mt < 2; mt++) {
        #pragma unroll
        for (int half = 0; half < 2; half++) {
            const int row = bm + rl + mt * 16 + half * 8;
            #pragma unroll
            for (int nt = 0; nt < 8; nt++) {
                const int col = cbse + nt * 8;
                float ox = acc[mt][nt][half * 2]     + bias[col];
                float oy = acc[mt][nt][half * 2 + 1] + bias[col + 1];
                const size_t idx = (size_t)row * CDIM + col;
                const float2 rr = *reinterpret_cast<const float2*>(&residual[idx]);
                ox += rr.x; oy += rr.y;
                *reinterpret_cast<float2*>(&X1[idx]) = make_float2(ox, oy);
                acc[mt][nt][half * 2]     = ox;
                acc[mt][nt][half * 2 + 1] = oy;
                ss[mt][half] += ox * ox + oy * oy;
            }
        }
    }
    #pragma unroll
    for (int mt = 0; mt < 2; mt++)
        #pragma unroll
        for (int half = 0; half < 2; half++) {
            float v = ss[mt][half];
            v += __shfl_xor_sync(0xffffffffu, v, 1);
            v += __shfl_xor_sync(0xffffffffu, v, 2);
            if ((lane & 3) == 0)
                sredn[(rl + mt * 16 + half * 8) * 4 + wn] = v;
        }
    __syncthreads();

    #pragma unroll
    for (int mt = 0; mt < 2; mt++) {
        #pragma unroll
        for (int half = 0; half < 2; half++) {
            const int rloc = rl + mt * 16 + half * 8;
            const float tot = sredn[rloc * 4 + 0] + sredn[rloc * 4 + 1]
                            + sredn[rloc * 4 + 2] + sredn[rloc * 4 + 3];
            const float r = rsqrtf(tot * (1.0f / CDIM) + 1e-6f);
            const int row = bm + rloc;
            #pragma unroll
            for (int nt = 0; nt < 8; nt++) {
                const int col = cbse + nt * 8;
                const float2 wv = *reinterpret_cast<const float2*>(&n2w[col]);
                *reinterpret_cast<__nv_bfloat162*>(&N2[(size_t)row * CDIM + col]) =
                    __floats2bfloat162_rn(acc[mt][nt][half * 2] * r * wv.x,
                                          acc[mt][nt][half * 2 + 1] * r * wv.y);
            }
        }
    }
}

// ---------------------------------------------------------------------------
// ff1 GEMM (permuted columns) + bias + fused GeGLU epilogue -> g (bf16).
// BM=64, BN=128, 256 threads (8 warps: 2M x 4N, warp 32x32).
// Within a CTA: cols 0..63 = gate block, 64..127 = matching value block.
// ---------------------------------------------------------------------------
#define F1_STG  24576u            // 8KB A + 16KB B per stage
#define F1_SIZE 49152

__global__ __launch_bounds__(256, 3)
void ff1_geglu_kernel(const __nv_bfloat16* __restrict__ A,
                      const __nv_bfloat16* __restrict__ Bt,
                      const float* __restrict__ bias,   // ORIGINAL ff1_b
                      __nv_bfloat16* __restrict__ G)
{
    extern __shared__ __align__(1024) char smem[];
    const uint32_t sb = smem_u32(smem);
    float* vred = reinterpret_cast<float*>(smem);     // [64][64] fp32 (stage0)
    const int tid  = threadIdx.x;
    const int wid  = tid >> 5;
    const int lane = tid & 31;
    const int bm   = blockIdx.y * 64;
    const int bn   = blockIdx.x * 128;                // permuted col space
    const int wm   = wid & 1;
    const int wn   = wid >> 1;                        // 0..3, 32 cols each
    const int lrow = tid >> 3;
    const int lch  = tid & 7;

    #define F1_LOAD(kc, stage) do {                                              \
        const uint32_t s0 = (uint32_t)(stage) * F1_STG;                          \
        _Pragma("unroll")                                                        \
        for (int it = 0; it < 2; it++) {                                         \
            const int row = it * 32 + lrow;                                      \
            uint32_t off = swz((uint32_t)row * 128u + (uint32_t)lch * 16u);      \
            CP_ASYNC16(sb + s0 + off,                                            \
                       A + (size_t)(bm + row) * GK + (kc) * 64 + lch * 8);       \
        }                                                                        \
        _Pragma("unroll")                                                        \
        for (int it = 0; it < 4; it++) {                                         \
            const int row = it * 32 + lrow;                                      \
            uint32_t off = swz((uint32_t)row * 128u + (uint32_t)lch * 16u);      \
            CP_ASYNC16(sb + s0 + 8192u + off,                                    \
                       Bt + (size_t)(bn + row) * GK + (kc) * 64 + lch * 8);      \
        }                                                                        \
        CP_COMMIT();                                                             \
    } while (0)

    F1_LOAD(0, 0);
    F1_LOAD(1, 1);

    float acc[2][4][4] = {};
    const int mtx = lane >> 3;
    const int l7  = lane & 7;

    #pragma unroll
    for (int kc = 0; kc < 4; kc++) {
        if (kc < 3) CP_WAIT(1); else CP_WAIT(0);
        __syncthreads();
        const uint32_t sA = sb + (uint32_t)(kc & 1) * F1_STG;
        const uint32_t sB = sA + 8192u;

        #pragma unroll
        for (int s16 = 0; s16 < 4; s16++) {
            const int chunk0 = s16 * 2;
            uint32_t af[2][4];
            #pragma unroll
            for (int mt = 0; mt < 2; mt++) {
                const int row   = wm * 32 + mt * 16 + (mtx & 1) * 8 + l7;
                const int chunk = chunk0 + (mtx >> 1);
                LDMATRIX_X4(af[mt][0], af[mt][1], af[mt][2], af[mt][3],
                            sA + swz((uint32_t)row * 128u + (uint32_t)chunk * 16u));
            }
            uint32_t bf[4][2];
            #pragma unroll
            for (int pair = 0; pair < 2; pair++) {
                const int nrow  = wn * 32 + pair * 16 + (mtx >> 1) * 8 + l7;
                const int chunk = chunk0 + (mtx & 1);
                LDMATRIX_X4(bf[pair * 2][0], bf[pair * 2][1],
                            bf[pair * 2 + 1][0], bf[pair * 2 + 1][1],
                            sB + swz((uint32_t)nrow * 128u + (uint32_t)chunk * 16u));
            }
            #pragma unroll
            for (int mt = 0; mt < 2; mt++)
                #pragma unroll
                for (int nt = 0; nt < 4; nt++)
                    MMA_BF16(acc[mt][nt], af[mt], bf[nt]);
        }
        __syncthreads();
        if (kc < 2) F1_LOAD(kc + 2, kc & 1);
    }
    #undef F1_LOAD

    // ---- epilogue: add (permuted) bias; value warps -> smem; gate warps geglu
    const int rl   = wm * 32 + (lane >> 2);
    const int cloc = wn * 32 + (lane & 3) * 2;        // 0..127 within CTA
    #pragma unroll
    for (int mt = 0; mt < 2; mt++) {
        #pragma unroll
        for (int half = 0; half < 2; half++) {
            #pragma unroll
            for (int nt = 0; nt < 4; nt++) {
                const int c = cloc + nt * 8;
                acc[mt][nt][half * 2]     += bias[ff1_src(bn + c)];
                acc[mt][nt][half * 2 + 1] += bias[ff1_src(bn + c + 1)];
            }
        }
    }
    if (wn >= 2) {                                    // value cols 64..127
        #pragma unroll
        for (int mt = 0; mt < 2; mt++)
            #pragma unroll
            for (int half = 0; half < 2; half++) {
                const int row = rl + mt * 16 + half * 8;
                #pragma unroll
                for (int nt = 0; nt < 4; nt++) {
                    const int j = cloc + nt * 8 - 64;
                    *reinterpret_cast<float2*>(&vred[row * 64 + j]) =
                        make_float2(acc[mt][nt][half * 2], acc[mt][nt][half * 2 + 1]);
                }
            }
    }
    __syncthreads();
    if (wn < 2) {                                     // gate cols 0..63
        #pragma unroll
        for (int mt = 0; mt < 2; mt++)
            #pragma unroll
            for (int half = 0; half < 2; half++) {
                const int row = rl + mt * 16 + half * 8;
                #pragma unroll
                for (int nt = 0; nt < 4; nt++) {
                    const int j = cloc + nt * 8;
                    const float2 vv = *reinterpret_cast<const float2*>(&vred[row * 64 + j]);
                    const float g0 = acc[mt][nt][half * 2];
                    const float g1 = acc[mt][nt][half * 2 + 1];
                    const float e0 = 0.5f * g0 * (1.0f + erff(g0 * 0.70710678118654752f));
                    const float e1 = 0.5f * g1 * (1.0f + erff(g1 * 0.70710678118654752f));
                    *reinterpret_cast<__nv_bfloat162*>(
                        &G[(size_t)(bm + row) * CDIM + blockIdx.x * 64 + j]) =
                        __floats2bfloat162_rn(e0 * vv.x, e1 * vv.y);
                }
            }
    }
}

// ---------------------------------------------------------------------------
// Tiled tensor-core neighborhood attention (unchanged from R8).
// ---------------------------------------------------------------------------
#define AT_Q    0
#define AT_K    8192
#define AT_V    36864
#define AT_RED  8192
#define AT_MAX  65536
#define AT_SUM  66048
#define AT_SIZE 66560
#define REDW    68

__global__ __launch_bounds__(256, 2)
void attn_mma_kernel(const __nv_bfloat16* __restrict__ qkv,
                     __nv_bfloat16* __restrict__ out)
{
    extern __shared__ __align__(1024) char smem[];
    const uint32_t sb = smem_u32(smem);
    float* smax = reinterpret_cast<float*>(smem + AT_MAX);
    float* ssum = reinterpret_cast<float*>(smem + AT_SUM);
    float* sred = reinterpret_cast<float*>(smem + AT_RED);

    const int tid  = threadIdx.x;
    const int wid  = tid >> 5;
    const int lane = tid & 31;
    const int head = blockIdx.y;
    const int b    = blockIdx.z;
    const int ty0  = (blockIdx.x >> 3) * 8;
    const int tx0  = (blockIdx.x & 7) * 8;
    const int ny0  = min(max(ty0 - 3, 0), 50);
    const int nx0  = min(max(tx0 - 3, 0), 50);

    const __nv_bfloat16* base = qkv + (size_t)b * 4096 * QKVN + head * 64;

    #pragma unroll
    for (int i = 0; i < 2; i++) {
        const int idx = i * 256 + tid;
        const int m = idx >> 3, ch = idx & 7;
        const int y = ty0 + (m >> 3), x = tx0 + (m & 7);
        uint32_t off = swz((uint32_t)m * 128u + (uint32_t)ch * 16u);
        CP_ASYNC16(sb + AT_Q + off, base + (size_t)(y * 64 + x) * QKVN + ch * 8);
    }
    CP_COMMIT();
    #pragma unroll
    for (int i = 0; i < 7; i++) {
        const int idx = i * 256 + tid;
        const int kv = idx >> 3, ch = idx & 7;
        const int r = kv >> 4, c = kv & 15;
        uint32_t off = swz((uint32_t)kv * 128u + (uint32_t)ch * 16u);
        if (c < 14)
            CP_ASYNC16(sb + AT_K + off,
                       base + (size_t)((ny0 + r) * 64 + nx0 + c) * QKVN + CDIM + ch * 8);
        else
            *reinterpret_cast<uint4*>(smem + AT_K + off) = make_uint4(0, 0, 0, 0);
    }
    CP_COMMIT();
    #pragma unroll
    for (int i = 0; i < 7; i++) {
        const int idx = i * 256 + tid;
        const int kv = idx >> 3, ch = idx & 7;
        const int r = kv >> 4, c = kv & 15;
        uint32_t off = swz((uint32_t)kv * 128u + (uint32_t)ch * 16u);
        if (c < 14)
            CP_ASYNC16(sb + AT_V + off,
                       base + (size_t)((ny0 + r) * 64 + nx0 + c) * QKVN + 2 * CDIM + ch * 8);
        else
            *reinterpret_cast<uint4*>(smem + AT_V + off) = make_uint4(0, 0, 0, 0);
    }
    CP_COMMIT();

    const int wm  = wid & 3;
    const int wn  = wid >> 2;
    const int mtx = lane >> 3;
    const int l7  = lane & 7;

    CP_WAIT(1);
    __syncthreads();

    uint32_t af[4][4];
    #pragma unroll
    for (int k16 = 0; k16 < 4; k16++) {
        const int row   = wm * 16 + (mtx & 1) * 8 + l7;
        const int chunk = k16 * 2 + (mtx >> 1);
        LDMATRIX_X4(af[k16][0], af[k16][1], af[k16][2], af[k16][3],
                    sb + AT_Q + swz((uint32_t)row * 128u + (uint32_t)chunk * 16u));
    }

    float acc[14][4] = {};
    #pragma unroll
    for (int k16 = 0; k16 < 4; k16++) {
        #pragma unroll
        for (int grp = 0; grp < 2; grp++) {
            const int nt0    = grp * 8;
            const int npairs = grp ? 3 : 4;
            uint32_t bf[8][2];
            #pragma unroll
            for (int pair = 0; pair < 4; pair++) {
                if (pair < npairs) {
                    const int nrow  = wn * 112 + (nt0 + pair * 2) * 8 + (mtx >> 1) * 8 + l7;
                    const int chunk = k16 * 2 + (mtx & 1);
                    LDMATRIX_X4(bf[pair * 2][0], bf[pair * 2][1],
                                bf[pair * 2 + 1][0], bf[pair * 2 + 1][1],
                                sb + AT_K + swz((uint32_t)nrow * 128u + (uint32_t)chunk * 16u));
                }
            }
            const int ntiles = grp ? 6 : 8;
            #pragma unroll
            for (int j = 0; j < 8; j++)
                if (j < ntiles)
                    MMA_BF16(acc[nt0 + j], af[k16], bf[j]);
        }
    }

    const int row0 = wm * 16 + (lane >> 2);
    const int row1 = row0 + 8;
    const int y_a = ty0 + (row0 >> 3), x_a = tx0 + (row0 & 7);
    const int y_b = ty0 + (row1 >> 3), x_b = tx0 + (row1 & 7);
    const int rlo_a = min(max(y_a - 3, 0), 57) - ny0;
    const int clo_a = min(max(x_a - 3, 0), 57) - nx0;
    const int rlo_b = min(max(y_b - 3, 0), 57) - ny0;
    const int clo_b = min(max(x_b - 3, 0), 57) - nx0;

    uint32_t vm_a = 0, vm_b = 0;
    #pragma unroll
    for (int nt = 0; nt < 14; nt++) {
        #pragma unroll
        for (int j = 0; j < 2; j++) {
            const int n = wn * 112 + nt * 8 + (lane & 3) * 2 + j;
            const int r = n >> 4, c = n & 15;
            if (c < 14 && (unsigned)(r - rlo_a) < 7u && (unsigned)(c - clo_a) < 7u)
                vm_a |= 1u << (nt * 2 + j);
            if (c < 14 && (unsigned)(r - rlo_b) < 7u && (unsigned)(c - clo_b) < 7u)
                vm_b |= 1u << (nt * 2 + j);
        }
    }

    float mx_a = -3e38f, mx_b = -3e38f;
    #pragma unroll
    for (int nt = 0; nt < 14; nt++) {
        #pragma unroll
        for (int j = 0; j < 2; j++) {
            if (vm_a & (1u << (nt * 2 + j))) mx_a = fmaxf(mx_a, acc[nt][j]);
            if (vm_b & (1u << (nt * 2 + j))) mx_b = fmaxf(mx_b, acc[nt][2 + j]);
        }
    }
    mx_a = fmaxf(mx_a, __shfl_xor_sync(0xffffffffu, mx_a, 1));
    mx_a = fmaxf(mx_a, __shfl_xor_sync(0xffffffffu, mx_a, 2));
    mx_b = fmaxf(mx_b, __shfl_xor_sync(0xffffffffu, mx_b, 1));
    mx_b = fmaxf(mx_b, __shfl_xor_sync(0xffffffffu, mx_b, 2));
    if ((lane & 3) == 0) {
        smax[row0 * 2 + wn] = mx_a;
        smax[row1 * 2 + wn] = mx_b;
    }
    __syncthreads();
    const float M_a = fmaxf(smax[row0 * 2], smax[row0 * 2 + 1]);
    const float M_b = fmaxf(smax[row1 * 2], smax[row1 * 2 + 1]);

    const float SC = 0.18033688011112042f;
    float sm_a = 0.0f, sm_b = 0.0f;
    #pragma unroll
    for (int nt = 0; nt < 14; nt++) {
        #pragma unroll
        for (int j = 0; j < 2; j++) {
            float ea = (vm_a & (1u << (nt * 2 + j)))
                     ? exp2f((acc[nt][j] - M_a) * SC) : 0.0f;
            float eb = (vm_b & (1u << (nt * 2 + j)))
                     ? exp2f((acc[nt][2 + j] - M_b) * SC) : 0.0f;
            acc[nt][j] = ea; acc[nt][2 + j] = eb;
            sm_a += ea; sm_b += eb;
        }
    }
    sm_a += __shfl_xor_sync(0xffffffffu, sm_a, 1);
    sm_a += __shfl_xor_sync(0xffffffffu, sm_a, 2);
    sm_b += __shfl_xor_sync(0xffffffffu, sm_b, 1);
    sm_b += __shfl_xor_sync(0xffffffffu, sm_b, 2);
    if ((lane & 3) == 0) {
        ssum[row0 * 2 + wn] = sm_a;
        ssum[row1 * 2 + wn] = sm_b;
    }

    uint32_t pf[7][4];
    #pragma unroll
    for (int s = 0; s < 7; s++) {
        pf[s][0] = packbf(acc[2 * s][0],     acc[2 * s][1]);
        pf[s][1] = packbf(acc[2 * s][2],     acc[2 * s][3]);
        pf[s][2] = packbf(acc[2 * s + 1][0], acc[2 * s + 1][1]);
        pf[s][3] = packbf(acc[2 * s + 1][2], acc[2 * s + 1][3]);
    }

    CP_WAIT(0);
    __syncthreads();

    float accO[8][4] = {};
    #pragma unroll
    for (int s = 0; s < 7; s++) {
        uint32_t vf[8][2];
        #pragma unroll
        for (int g2 = 0; g2 < 4; g2++) {
            const int kvrow = (wn * 7 + s) * 16 + (lane & 15);
            const int colb  = (g2 * 16 + (lane >> 4) * 8) * 2;
            LDMATRIX_X4_TRANS(vf[g2 * 2][0], vf[g2 * 2][1],
                              vf[g2 * 2 + 1][0], vf[g2 * 2 + 1][1],
                              sb + AT_V + swz((uint32_t)kvrow * 128u + (uint32_t)colb));
        }
        #pragma unroll
        for (int nt = 0; nt < 8; nt++)
            MMA_BF16(accO[nt], pf[s], vf[nt]);
    }

    if (wn == 1) {
        #pragma unroll
        for (int nt = 0; nt < 8; nt++) {
            const int col = nt * 8 + (lane & 3) * 2;
            *reinterpret_cast<float2*>(&sred[row0 * REDW + col]) =
                make_float2(accO[nt][0], accO[nt][1]);
            *reinterpret_cast<float2*>(&sred[row1 * REDW + col]) =
                make_float2(accO[nt][2], accO[nt][3]);
        }
    }
    __syncthreads();

    if (wn == 0) {
        const float inv_a = 1.0f / (ssum[row0 * 2] + ssum[row0 * 2 + 1]);
        const float inv_b = 1.0f / (ssum[row1 * 2] + ssum[row1 * 2 + 1]);
        const size_t t_a = (size_t)b * 4096 + (size_t)(y_a * 64 + x_a);
        const size_t t_b = (size_t)b * 4096 + (size_t)(y_b * 64 + x_b);
        #pragma unroll
        for (int nt = 0; nt < 8; nt++) {
            const int col = nt * 8 + (lane & 3) * 2;
            const float2 ra = *reinterpret_cast<const float2*>(&sred[row0 * REDW + col]);
            const float2 rb = *reinterpret_cast<const float2*>(&sred[row1 * REDW + col]);
            *reinterpret_cast<__nv_bfloat162*>(out + t_a * CDIM + head * 64 + col) =
                __floats2bfloat162_rn((accO[nt][0] + ra.x) * inv_a,
                                      (accO[nt][1] + ra.y) * inv_a);
            *reinterpret_cast<__nv_bfloat162*>(out + t_b * CDIM + head * 64 + col) =
                __floats2bfloat162_rn((accO[nt][2] + rb.x) * inv_b,
                                      (accO[nt][3] + rb.y) * inv_b);
        }
    }
}

// ---------------------------------------------------------------------------
// Launch: 7 kernels.
// ---------------------------------------------------------------------------
extern "C" void kernel_launch(void* const* d_in, const int* in_sizes, int n_in,
                              void* d_out, int out_size)
{
    const float* x       = (const float*)d_in[0];
    const float* norm1_w = (const float*)d_in[1];
    const float* norm2_w = (const float*)d_in[2];
    const float* w_qkv   = (const float*)d_in[3];
    const float* w_proj  = (const float*)d_in[4];
    const float* b_proj  = (const float*)d_in[5];
    const float* ff1_w   = (const float*)d_in[6];
    const float* ff1_b   = (const float*)d_in[7];
    const float* ff2_w   = (const float*)d_in[8];
    const float* ff2_b   = (const float*)d_in[9];
    float* out = (float*)d_out;

    __nv_bfloat16 *p_h, *p_qkv, *p_attn, *p_n2, *p_g;
    __nv_bfloat16 *p_wqkvT, *p_wprojT, *p_ff1T, *p_ff2T;
    float *p_x1;
    cudaGetSymbolAddress((void**)&p_h,      g_h);
    cudaGetSymbolAddress((void**)&p_qkv,    g_qkv);
    cudaGetSymbolAddress((void**)&p_attn,   g_attn);
    cudaGetSymbolAddress((void**)&p_x1,     g_x1);
    cudaGetSymbolAddress((void**)&p_n2,     g_n2);
    cudaGetSymbolAddress((void**)&p_g,      g_g);
    cudaGetSymbolAddress((void**)&p_wqkvT,  g_wqkvT);
    cudaGetSymbolAddress((void**)&p_wprojT, g_wprojT);
    cudaGetSymbolAddress((void**)&p_ff1T,   g_ff1T);
    cudaGetSymbolAddress((void**)&p_ff2T,   g_ff2T);

    cudaFuncSetAttribute(gemm_mma_kernel,
                         cudaFuncAttributeMaxDynamicSharedMemorySize, SM_SIZE);
    cudaFuncSetAttribute(proj_norm_kernel,
                         cudaFuncAttributeMaxDynamicSharedMemorySize, PJ_SIZE);
    cudaFuncSetAttribute(ff1_geglu_kernel,
                         cudaFuncAttributeMaxDynamicSharedMemorySize, F1_SIZE);
    cudaFuncSetAttribute(attn_mma_kernel,
                         cudaFuncAttributeMaxDynamicSharedMemorySize, AT_SIZE);

    // 1. weight transposes (ff1 permuted)
    transpose_all_kernel<<<dim3(56, 8), dim3(32, 8)>>>(
        w_qkv, p_wqkvT, w_proj, p_wprojT, ff1_w, p_ff1T, ff2_w, p_ff2T);

    // 2. h = rope2d(rmsnorm(x, n1)) -> bf16
    rmsnorm_rope_kernel<<<NTOK, 128>>>(x, norm1_w, p_h);

    // 3. qkv = h @ w_qkv -> bf16
    gemm_mma_kernel<<<dim3(QKVN / 64, NTOK / 64), 128, SM_SIZE>>>(
        p_h, p_wqkvT, nullptr, nullptr, nullptr, p_qkv, QKVN, 0);

    // 4. attention -> bf16
    attn_mma_kernel<<<dim3(64, 4, 2), 256, AT_SIZE>>>(p_qkv, p_attn);

    // 5. x1 = x + attn @ w_proj + b_proj;  n2 = rmsnorm(x1, n2w)   (fused)
    proj_norm_kernel<<<NTOK / 64, 256, PJ_SIZE>>>(
        p_attn, p_wprojT, b_proj, x, norm2_w, p_x1, p_n2);

    // 6. g = geglu(n2 @ ff1_w_perm + ff1_b)                        (fused)
    ff1_geglu_kernel<<<dim3(4, NTOK / 64), 256, F1_SIZE>>>(
        p_n2, p_ff1T, ff1_b, p_g);

    // 7. out = x1 + g @ ff2_w + ff2_b
    gemm_mma_kernel<<<dim3(CDIM / 64, NTOK / 64), 128, SM_SIZE>>>(
        p_g, p_ff2T, ff2_b, p_x1, out, nullptr, CDIM, 2);
}

// round 12
// speedup vs baseline: 2.0595x; 1.0955x over previous
#include <cuda_runtime.h>
#include <cuda_bf16.h>
#include <math.h>
#include <stdint.h>

// ---------------------------------------------------------------------------
// Problem constants (B=2, H=W=64, C=256, nh=4, hd=64, k=7)
// ---------------------------------------------------------------------------
#define NTOK   8192
#define CDIM   256
#define GK     256
#define QKVN   768
#define FFN    512
#define KS     7
#define KK     49

// ---------------------------------------------------------------------------
// Scratch (__device__ globals; allocation forbidden)
// ---------------------------------------------------------------------------
__device__ __nv_bfloat16 g_h   [NTOK * CDIM];
__device__ __nv_bfloat16 g_qkv [NTOK * QKVN];
__device__ __nv_bfloat16 g_attn[NTOK * CDIM];
__device__ float         g_x1  [NTOK * CDIM];
__device__ __nv_bfloat16 g_n2  [NTOK * CDIM];
__device__ __nv_bfloat16 g_g   [NTOK * CDIM];
__device__ __nv_bfloat16 g_wqkvT[QKVN * GK];
__device__ __nv_bfloat16 g_wprojT[CDIM * GK];
__device__ __nv_bfloat16 g_ff1T [FFN  * GK];   // PERMUTED column order
__device__ __nv_bfloat16 g_ff2T [CDIM * GK];

// ---------------------------------------------------------------------------
// PTX helpers
// ---------------------------------------------------------------------------
__device__ __forceinline__ uint32_t smem_u32(const void* p) {
    uint32_t a;
    asm("{ .reg .u64 t; cvta.to.shared.u64 t, %1; cvt.u32.u64 %0, t; }"
        : "=r"(a) : "l"(p));
    return a;
}
#define LDMATRIX_X4(r0, r1, r2, r3, a) \
    asm volatile("ldmatrix.sync.aligned.m8n8.x4.shared.b16 {%0,%1,%2,%3}, [%4];" \
                 : "=r"(r0), "=r"(r1), "=r"(r2), "=r"(r3) : "r"(a))
#define LDMATRIX_X4_TRANS(r0, r1, r2, r3, a) \
    asm volatile("ldmatrix.sync.aligned.m8n8.x4.trans.shared.b16 {%0,%1,%2,%3}, [%4];" \
                 : "=r"(r0), "=r"(r1), "=r"(r2), "=r"(r3) : "r"(a))
#define MMA_BF16(d, a, b) \
    asm volatile("mma.sync.aligned.m16n8k16.row.col.f32.bf16.bf16.f32 " \
                 "{%0,%1,%2,%3}, {%4,%5,%6,%7}, {%8,%9}, {%0,%1,%2,%3};" \
                 : "+f"((d)[0]), "+f"((d)[1]), "+f"((d)[2]), "+f"((d)[3]) \
                 : "r"((a)[0]), "r"((a)[1]), "r"((a)[2]), "r"((a)[3]), \
                   "r"((b)[0]), "r"((b)[1]))
#define CP_ASYNC16(dst, src) \
    asm volatile("cp.async.cg.shared.global [%0], [%1], 16;" :: "r"(dst), "l"(src))
#define CP_COMMIT() asm volatile("cp.async.commit_group;" ::: "memory")
#define CP_WAIT(n)  asm volatile("cp.async.wait_group %0;" :: "n"(n) : "memory")

__device__ __forceinline__ uint32_t swz(uint32_t off) { return off ^ ((off >> 3) & 0x70); }
__device__ __forceinline__ uint32_t packbf(float a, float b) {
    __nv_bfloat162 h = __floats2bfloat162_rn(a, b);
    return *reinterpret_cast<uint32_t*>(&h);
}
// ff1 permutation: out col n -> source col of ff1_w
__device__ __forceinline__ int ff1_src(int n) {
    const int within = n & 127, blk = n >> 7;
    return (within < 64) ? (blk * 64 + within) : (256 + blk * 64 + within - 64);
}

// ---------------------------------------------------------------------------
// prep_kernel: weight transposes (ff1 permuted) + rmsnorm1+rope, ONE launch.
// Blocks [0,448): transpose tiles (wtile = bx>>3, k0 = (bx&7)*32).
// Blocks [448, 448+4096): rmsnorm+rope, 2 tokens per block.
// ---------------------------------------------------------------------------
__global__ void prep_kernel(const float* __restrict__ w0, __nv_bfloat16* __restrict__ o0,
                            const float* __restrict__ w1, __nv_bfloat16* __restrict__ o1,
                            const float* __restrict__ w2, __nv_bfloat16* __restrict__ o2,
                            const float* __restrict__ w3, __nv_bfloat16* __restrict__ o3,
                            const float* __restrict__ x,  const float* __restrict__ n1w,
                            __nv_bfloat16* __restrict__ h)
{
    const int bx  = blockIdx.x;
    const int tid = threadIdx.x;
    __shared__ float t[32][33];
    __shared__ float red[2][4];

    if (bx < 448) {
        const int wtile = bx >> 3;
        const int k0    = (bx & 7) * 32;
        const float* w; __nv_bfloat16* o; int N, nb; bool perm = false;
        if      (wtile < 24) { w = w0; o = o0; N = QKVN; nb = wtile;      }
        else if (wtile < 32) { w = w1; o = o1; N = CDIM; nb = wtile - 24; }
        else if (wtile < 48) { w = w2; o = o2; N = FFN;  nb = wtile - 32; perm = true; }
        else                 { w = w3; o = o3; N = CDIM; nb = wtile - 48; }

        const int n0 = nb * 32;
        const int s0 = perm ? ff1_src(n0) : n0;
        const int tx = tid & 31, ty = tid >> 5;
        #pragma unroll
        for (int i = 0; i < 32; i += 8)
            t[ty + i][tx] = w[(size_t)(k0 + ty + i) * N + s0 + tx];
        __syncthreads();
        #pragma unroll
        for (int i = 0; i < 32; i += 8)
            o[(size_t)(n0 + ty + i) * GK + k0 + tx] = __float2bfloat16(t[tx][ty + i]);
        return;
    }

    // ---- rmsnorm1 + rope: 2 tokens per block ----
    const int tok  = (bx - 448) * 2 + (tid >> 7);
    const int i    = tid & 127;
    const int half = tid >> 7;
    float2 v = reinterpret_cast<const float2*>(x + (size_t)tok * CDIM)[i];

    float ss = v.x * v.x + v.y * v.y;
    #pragma unroll
    for (int off = 16; off; off >>= 1)
        ss += __shfl_xor_sync(0xffffffffu, ss, off);
    if ((i & 31) == 0) red[half][i >> 5] = ss;
    __syncthreads();
    const float r = rsqrtf((red[half][0] + red[half][1] + red[half][2] + red[half][3])
                           * (1.0f / CDIM) + 1e-6f);

    const float2 wv = reinterpret_cast<const float2*>(n1w)[i];
    float a = v.x * r * wv.x;
    float b = v.y * r * wv.y;

    const int yy = (tok >> 6) & 63;
    const int xx = tok & 63;
    const int j  = i & 63;
    const float pos = (i < 64) ? (float)yy : (float)xx;
    const float inv = exp2f((float)j * (-13.28771237954945f / 64.0f));
    float c, s;
    sincosf(pos * inv, &s, &c);
    reinterpret_cast<__nv_bfloat162*>(h + (size_t)tok * CDIM)[i] =
        __floats2bfloat162_rn(a * c - b * s, a * s + b * c);
}

// ---------------------------------------------------------------------------
// Generic mma.sync bf16 GEMM: BM=64, BN=64, 128 threads, ring 32KB.
// mode: 0 = bf16 out, 2 = fp32 +bias+residual
// ---------------------------------------------------------------------------
#define GS_STAGE 16384u
#define SM_SIZE  32768

__global__ __launch_bounds__(128, 5)
void gemm_mma_kernel(const __nv_bfloat16* __restrict__ A,
                     const __nv_bfloat16* __restrict__ Bt,
                     const float* __restrict__ bias,
                     const float* __restrict__ residual,
                     float* __restrict__ C,
                     __nv_bfloat16* __restrict__ Cb,
                     int N, int mode)
{
    extern __shared__ __align__(1024) char smem[];
    const uint32_t sb = smem_u32(smem);
    const int tid  = threadIdx.x;
    const int wid  = tid >> 5;
    const int lane = tid & 31;
    const int bm   = blockIdx.y * 64;
    const int bn   = blockIdx.x * 64;
    const int wm   = wid & 1;
    const int wn   = wid >> 1;
    const int lrow = tid >> 3;
    const int lch  = tid & 7;

    #define LOAD_CHUNK(kc, stage) do {                                           \
        const uint32_t s0 = (uint32_t)(stage) * GS_STAGE;                        \
        _Pragma("unroll")                                                        \
        for (int it = 0; it < 4; it++) {                                         \
            const int row = it * 16 + lrow;                                      \
            uint32_t off = swz((uint32_t)row * 128u + (uint32_t)lch * 16u);      \
            CP_ASYNC16(sb + s0 + off,                                            \
                       A  + (size_t)(bm + row) * GK + (kc) * 64 + lch * 8);      \
            CP_ASYNC16(sb + s0 + 8192u + off,                                    \
                       Bt + (size_t)(bn + row) * GK + (kc) * 64 + lch * 8);      \
        }                                                                        \
        CP_COMMIT();                                                             \
    } while (0)

    LOAD_CHUNK(0, 0);
    LOAD_CHUNK(1, 1);

    float acc[2][4][4] = {};
    const int mtx = lane >> 3;
    const int l7  = lane & 7;

    #pragma unroll
    for (int kc = 0; kc < 4; kc++) {
        if (kc < 3) CP_WAIT(1); else CP_WAIT(0);
        __syncthreads();
        const uint32_t sA = sb + (uint32_t)(kc & 1) * GS_STAGE;
        const uint32_t sB = sA + 8192u;

        #pragma unroll
        for (int s16 = 0; s16 < 4; s16++) {
            const int chunk0 = s16 * 2;
            uint32_t af[2][4];
            #pragma unroll
            for (int mt = 0; mt < 2; mt++) {
                const int row   = wm * 32 + mt * 16 + (mtx & 1) * 8 + l7;
                const int chunk = chunk0 + (mtx >> 1);
                LDMATRIX_X4(af[mt][0], af[mt][1], af[mt][2], af[mt][3],
                            sA + swz((uint32_t)row * 128u + (uint32_t)chunk * 16u));
            }
            uint32_t bf[4][2];
            #pragma unroll
            for (int pair = 0; pair < 2; pair++) {
                const int nrow  = wn * 32 + pair * 16 + (mtx >> 1) * 8 + l7;
                const int chunk = chunk0 + (mtx & 1);
                LDMATRIX_X4(bf[pair * 2][0], bf[pair * 2][1],
                            bf[pair * 2 + 1][0], bf[pair * 2 + 1][1],
                            sB + swz((uint32_t)nrow * 128u + (uint32_t)chunk * 16u));
            }
            #pragma unroll
            for (int mt = 0; mt < 2; mt++)
                #pragma unroll
                for (int nt = 0; nt < 4; nt++)
                    MMA_BF16(acc[mt][nt], af[mt], bf[nt]);
        }
        __syncthreads();
        if (kc < 2) LOAD_CHUNK(kc + 2, kc & 1);
    }
    #undef LOAD_CHUNK

    const int rbase = bm + wm * 32 + (lane >> 2);
    const int cbase = bn + wn * 32 + (lane & 3) * 2;
    #pragma unroll
    for (int mt = 0; mt < 2; mt++) {
        #pragma unroll
        for (int half = 0; half < 2; half++) {
            const int row = rbase + mt * 16 + half * 8;
            #pragma unroll
            for (int nt = 0; nt < 4; nt++) {
                const int col = cbase + nt * 8;
                float ox = acc[mt][nt][half * 2];
                float oy = acc[mt][nt][half * 2 + 1];
                const size_t idx = (size_t)row * N + col;
                if (mode == 0) {
                    *reinterpret_cast<__nv_bfloat162*>(&Cb[idx]) =
                        __floats2bfloat162_rn(ox, oy);
                } else {
                    ox += bias[col];
                    oy += bias[col + 1];
                    const float2 rr = *reinterpret_cast<const float2*>(&residual[idx]);
                    *reinterpret_cast<float2*>(&C[idx]) =
                        make_float2(ox + rr.x, oy + rr.y);
                }
            }
        }
    }
}

// ---------------------------------------------------------------------------
// proj GEMM + residual + fused RMSNorm2 epilogue (unchanged from R11).
// ---------------------------------------------------------------------------
#define PJ_STG  40960u
#define PJ_SIZE 81920

__global__ __launch_bounds__(256, 2)
void proj_norm_kernel(const __nv_bfloat16* __restrict__ A,
                      const __nv_bfloat16* __restrict__ Bt,
                      const float* __restrict__ bias,
                      const float* __restrict__ residual,
                      const float* __restrict__ n2w,
                      float* __restrict__ X1,
                      __nv_bfloat16* __restrict__ N2)
{
    extern __shared__ __align__(1024) char smem[];
    const uint32_t sb = smem_u32(smem);
    float* sredn = reinterpret_cast<float*>(smem);
    const int tid  = threadIdx.x;
    const int wid  = tid >> 5;
    const int lane = tid & 31;
    const int bm   = blockIdx.x * 64;
    const int wm   = wid & 1;
    const int wn   = wid >> 1;
    const int lrow = tid >> 3;
    const int lch  = tid & 7;

    #define PJ_LOAD(kc, stage) do {                                              \
        const uint32_t s0 = (uint32_t)(stage) * PJ_STG;                          \
        _Pragma("unroll")                                                        \
        for (int it = 0; it < 2; it++) {                                         \
            const int row = it * 32 + lrow;                                      \
            uint32_t off = swz((uint32_t)row * 128u + (uint32_t)lch * 16u);      \
            CP_ASYNC16(sb + s0 + off,                                            \
                       A + (size_t)(bm + row) * GK + (kc) * 64 + lch * 8);       \
        }                                                                        \
        _Pragma("unroll")                                                        \
        for (int it = 0; it < 8; it++) {                                         \
            const int row = it * 32 + lrow;                                      \
            uint32_t off = swz((uint32_t)row * 128u + (uint32_t)lch * 16u);      \
            CP_ASYNC16(sb + s0 + 8192u + off,                                    \
                       Bt + (size_t)row * GK + (kc) * 64 + lch * 8);             \
        }                                                                        \
        CP_COMMIT();                                                             \
    } while (0)

    PJ_LOAD(0, 0);
    PJ_LOAD(1, 1);

    float acc[2][8][4] = {};
    const int mtx = lane >> 3;
    const int l7  = lane & 7;

    #pragma unroll
    for (int kc = 0; kc < 4; kc++) {
        if (kc < 3) CP_WAIT(1); else CP_WAIT(0);
        __syncthreads();
        const uint32_t sA = sb + (uint32_t)(kc & 1) * PJ_STG;
        const uint32_t sB = sA + 8192u;

        #pragma unroll
        for (int s16 = 0; s16 < 4; s16++) {
            const int chunk0 = s16 * 2;
            uint32_t af[2][4];
            #pragma unroll
            for (int mt = 0; mt < 2; mt++) {
                const int row   = wm * 32 + mt * 16 + (mtx & 1) * 8 + l7;
                const int chunk = chunk0 + (mtx >> 1);
                LDMATRIX_X4(af[mt][0], af[mt][1], af[mt][2], af[mt][3],
                            sA + swz((uint32_t)row * 128u + (uint32_t)chunk * 16u));
            }
            uint32_t bf[8][2];
            #pragma unroll
            for (int pair = 0; pair < 4; pair++) {
                const int nrow  = wn * 64 + pair * 16 + (mtx >> 1) * 8 + l7;
                const int chunk = chunk0 + (mtx & 1);
                LDMATRIX_X4(bf[pair * 2][0], bf[pair * 2][1],
                            bf[pair * 2 + 1][0], bf[pair * 2 + 1][1],
                            sB + swz((uint32_t)nrow * 128u + (uint32_t)chunk * 16u));
            }
            #pragma unroll
            for (int mt = 0; mt < 2; mt++)
                #pragma unroll
                for (int nt = 0; nt < 8; nt++)
                    MMA_BF16(acc[mt][nt], af[mt], bf[nt]);
        }
        __syncthreads();
        if (kc < 2) PJ_LOAD(kc + 2, kc & 1);
    }
    #undef PJ_LOAD

    const int rl   = wm * 32 + (lane >> 2);
    const int cbse = wn * 64 + (lane & 3) * 2;
    float ss[2][2] = {};
    #pragma unroll
    for (int mt = 0; mt < 2; mt++) {
        #pragma unroll
        for (int half = 0; half < 2; half++) {
            const int row = bm + rl + mt * 16 + half * 8;
            #pragma unroll
            for (int nt = 0; nt < 8; nt++) {
                const int col = cbse + nt * 8;
                float ox = acc[mt][nt][half * 2]     + bias[col];
                float oy = acc[mt][nt][half * 2 + 1] + bias[col + 1];
                const size_t idx = (size_t)row * CDIM + col;
                const float2 rr = *reinterpret_cast<const float2*>(&residual[idx]);
                ox += rr.x; oy += rr.y;
                *reinterpret_cast<float2*>(&X1[idx]) = make_float2(ox, oy);
                acc[mt][nt][half * 2]     = ox;
                acc[mt][nt][half * 2 + 1] = oy;
                ss[mt][half] += ox * ox + oy * oy;
            }
        }
    }
    #pragma unroll
    for (int mt = 0; mt < 2; mt++)
        #pragma unroll
        for (int half = 0; half < 2; half++) {
            float v = ss[mt][half];
            v += __shfl_xor_sync(0xffffffffu, v, 1);
            v += __shfl_xor_sync(0xffffffffu, v, 2);
            if ((lane & 3) == 0)
                sredn[(rl + mt * 16 + half * 8) * 4 + wn] = v;
        }
    __syncthreads();

    #pragma unroll
    for (int mt = 0; mt < 2; mt++) {
        #pragma unroll
        for (int half = 0; half < 2; half++) {
            const int rloc = rl + mt * 16 + half * 8;
            const float tot = sredn[rloc * 4 + 0] + sredn[rloc * 4 + 1]
                            + sredn[rloc * 4 + 2] + sredn[rloc * 4 + 3];
            const float r = rsqrtf(tot * (1.0f / CDIM) + 1e-6f);
            const int row = bm + rloc;
            #pragma unroll
            for (int nt = 0; nt < 8; nt++) {
                const int col = cbse + nt * 8;
                const float2 wv = *reinterpret_cast<const float2*>(&n2w[col]);
                *reinterpret_cast<__nv_bfloat162*>(&N2[(size_t)row * CDIM + col]) =
                    __floats2bfloat162_rn(acc[mt][nt][half * 2] * r * wv.x,
                                          acc[mt][nt][half * 2 + 1] * r * wv.y);
            }
        }
    }
}

// ---------------------------------------------------------------------------
// ff1 GEMM (permuted columns) + bias + fused GeGLU epilogue (unchanged R11).
// ---------------------------------------------------------------------------
#define F1_STG  24576u
#define F1_SIZE 49152

__global__ __launch_bounds__(256, 3)
void ff1_geglu_kernel(const __nv_bfloat16* __restrict__ A,
                      const __nv_bfloat16* __restrict__ Bt,
                      const float* __restrict__ bias,
                      __nv_bfloat16* __restrict__ G)
{
    extern __shared__ __align__(1024) char smem[];
    const uint32_t sb = smem_u32(smem);
    float* vred = reinterpret_cast<float*>(smem);
    const int tid  = threadIdx.x;
    const int wid  = tid >> 5;
    const int lane = tid & 31;
    const int bm   = blockIdx.y * 64;
    const int bn   = blockIdx.x * 128;
    const int wm   = wid & 1;
    const int wn   = wid >> 1;
    const int lrow = tid >> 3;
    const int lch  = tid & 7;

    #define F1_LOAD(kc, stage) do {                                              \
        const uint32_t s0 = (uint32_t)(stage) * F1_STG;                          \
        _Pragma("unroll")                                                        \
        for (int it = 0; it < 2; it++) {                                         \
            const int row = it * 32 + lrow;                                      \
            uint32_t off = swz((uint32_t)row * 128u + (uint32_t)lch * 16u);      \
            CP_ASYNC16(sb + s0 + off,                                            \
                       A + (size_t)(bm + row) * GK + (kc) * 64 + lch * 8);       \
        }                                                                        \
        _Pragma("unroll")                                                        \
        for (int it = 0; it < 4; it++) {                                         \
            const int row = it * 32 + lrow;                                      \
            uint32_t off = swz((uint32_t)row * 128u + (uint32_t)lch * 16u);      \
            CP_ASYNC16(sb + s0 + 8192u + off,                                    \
                       Bt + (size_t)(bn + row) * GK + (kc) * 64 + lch * 8);      \
        }                                                                        \
        CP_COMMIT();                                                             \
    } while (0)

    F1_LOAD(0, 0);
    F1_LOAD(1, 1);

    float acc[2][4][4] = {};
    const int mtx = lane >> 3;
    const int l7  = lane & 7;

    #pragma unroll
    for (int kc = 0; kc < 4; kc++) {
        if (kc < 3) CP_WAIT(1); else CP_WAIT(0);
        __syncthreads();
        const uint32_t sA = sb + (uint32_t)(kc & 1) * F1_STG;
        const uint32_t sB = sA + 8192u;

        #pragma unroll
        for (int s16 = 0; s16 < 4; s16++) {
            const int chunk0 = s16 * 2;
            uint32_t af[2][4];
            #pragma unroll
            for (int mt = 0; mt < 2; mt++) {
                const int row   = wm * 32 + mt * 16 + (mtx & 1) * 8 + l7;
                const int chunk = chunk0 + (mtx >> 1);
                LDMATRIX_X4(af[mt][0], af[mt][1], af[mt][2], af[mt][3],
                            sA + swz((uint32_t)row * 128u + (uint32_t)chunk * 16u));
            }
            uint32_t bf[4][2];
            #pragma unroll
            for (int pair = 0; pair < 2; pair++) {
                const int nrow  = wn * 32 + pair * 16 + (mtx >> 1) * 8 + l7;
                const int chunk = chunk0 + (mtx & 1);
                LDMATRIX_X4(bf[pair * 2][0], bf[pair * 2][1],
                            bf[pair * 2 + 1][0], bf[pair * 2 + 1][1],
                            sB + swz((uint32_t)nrow * 128u + (uint32_t)chunk * 16u));
            }
            #pragma unroll
            for (int mt = 0; mt < 2; mt++)
                #pragma unroll
                for (int nt = 0; nt < 4; nt++)
                    MMA_BF16(acc[mt][nt], af[mt], bf[nt]);
        }
        __syncthreads();
        if (kc < 2) F1_LOAD(kc + 2, kc & 1);
    }
    #undef F1_LOAD

    const int rl   = wm * 32 + (lane >> 2);
    const int cloc = wn * 32 + (lane & 3) * 2;
    #pragma unroll
    for (int mt = 0; mt < 2; mt++) {
        #pragma unroll
        for (int half = 0; half < 2; half++) {
            #pragma unroll
            for (int nt = 0; nt < 4; nt++) {
                const int c = cloc + nt * 8;
                acc[mt][nt][half * 2]     += bias[ff1_src(bn + c)];
                acc[mt][nt][half * 2 + 1] += bias[ff1_src(bn + c + 1)];
            }
        }
    }
    if (wn >= 2) {
        #pragma unroll
        for (int mt = 0; mt < 2; mt++)
            #pragma unroll
            for (int half = 0; half < 2; half++) {
                const int row = rl + mt * 16 + half * 8;
                #pragma unroll
                for (int nt = 0; nt < 4; nt++) {
                    const int j = cloc + nt * 8 - 64;
                    *reinterpret_cast<float2*>(&vred[row * 64 + j]) =
                        make_float2(acc[mt][nt][half * 2], acc[mt][nt][half * 2 + 1]);
                }
            }
    }
    __syncthreads();
    if (wn < 2) {
        #pragma unroll
        for (int mt = 0; mt < 2; mt++)
            #pragma unroll
            for (int half = 0; half < 2; half++) {
                const int row = rl + mt * 16 + half * 8;
                #pragma unroll
                for (int nt = 0; nt < 4; nt++) {
                    const int j = cloc + nt * 8;
                    const float2 vv = *reinterpret_cast<const float2*>(&vred[row * 64 + j]);
                    const float g0 = acc[mt][nt][half * 2];
                    const float g1 = acc[mt][nt][half * 2 + 1];
                    const float e0 = 0.5f * g0 * (1.0f + erff(g0 * 0.70710678118654752f));
                    const float e1 = 0.5f * g1 * (1.0f + erff(g1 * 0.70710678118654752f));
                    *reinterpret_cast<__nv_bfloat162*>(
                        &G[(size_t)(bm + row) * CDIM + blockIdx.x * 64 + j]) =
                        __floats2bfloat162_rn(e0 * vv.x, e1 * vv.y);
                }
            }
    }
}

// ---------------------------------------------------------------------------
// Neighborhood attention, 4x8 token tile (32 tokens), halo 10x14 -> 160 kv.
// 128 threads (4 warps): wm 0..1 (16 token rows), wn 0..1 (80 kv half).
// ---------------------------------------------------------------------------
#define AT_Q    0
#define AT_K    4096
#define AT_V    24576
#define AT_RED  4096              // overlays K (dead after phase 1)
#define AT_MAX  45056
#define AT_SUM  45312
#define AT_SIZE 45568
#define REDW    68

__global__ __launch_bounds__(128, 5)
void attn_mma_kernel(const __nv_bfloat16* __restrict__ qkv,
                     __nv_bfloat16* __restrict__ out)
{
    extern __shared__ __align__(1024) char smem[];
    const uint32_t sb = smem_u32(smem);
    float* smax = reinterpret_cast<float*>(smem + AT_MAX);   // [32][2]
    float* ssum = reinterpret_cast<float*>(smem + AT_SUM);   // [32][2]
    float* sred = reinterpret_cast<float*>(smem + AT_RED);

    const int tid  = threadIdx.x;
    const int wid  = tid >> 5;
    const int lane = tid & 31;
    const int head = blockIdx.y;
    const int b    = blockIdx.z;
    const int ty0  = (blockIdx.x >> 3) * 4;     // 16 y-tiles of 4 rows
    const int tx0  = (blockIdx.x & 7) * 8;      // 8 x-tiles of 8 cols
    const int ny0  = min(max(ty0 - 3, 0), 54);  // 10 halo rows
    const int nx0  = min(max(tx0 - 3, 0), 50);  // 14 halo cols

    const __nv_bfloat16* base = qkv + (size_t)b * 4096 * QKVN + head * 64;

    // ---- async loads: Q (32 rows), K (160), V (160) ----
    #pragma unroll
    for (int i = 0; i < 2; i++) {
        const int idx = i * 128 + tid;
        const int m = idx >> 3, ch = idx & 7;
        const int y = ty0 + (m >> 3), x = tx0 + (m & 7);
        uint32_t off = swz((uint32_t)m * 128u + (uint32_t)ch * 16u);
        CP_ASYNC16(sb + AT_Q + off, base + (size_t)(y * 64 + x) * QKVN + ch * 8);
    }
    CP_COMMIT();
    #pragma unroll
    for (int i = 0; i < 10; i++) {
        const int idx = i * 128 + tid;
        const int kv = idx >> 3, ch = idx & 7;
        const int r = kv >> 4, c = kv & 15;
        uint32_t off = swz((uint32_t)kv * 128u + (uint32_t)ch * 16u);
        if (c < 14)
            CP_ASYNC16(sb + AT_K + off,
                       base + (size_t)((ny0 + r) * 64 + nx0 + c) * QKVN + CDIM + ch * 8);
        else
            *reinterpret_cast<uint4*>(smem + AT_K + off) = make_uint4(0, 0, 0, 0);
    }
    CP_COMMIT();
    #pragma unroll
    for (int i = 0; i < 10; i++) {
        const int idx = i * 128 + tid;
        const int kv = idx >> 3, ch = idx & 7;
        const int r = kv >> 4, c = kv & 15;
        uint32_t off = swz((uint32_t)kv * 128u + (uint32_t)ch * 16u);
        if (c < 14)
            CP_ASYNC16(sb + AT_V + off,
                       base + (size_t)((ny0 + r) * 64 + nx0 + c) * QKVN + 2 * CDIM + ch * 8);
        else
            *reinterpret_cast<uint4*>(smem + AT_V + off) = make_uint4(0, 0, 0, 0);
    }
    CP_COMMIT();

    const int wm  = wid & 1;
    const int wn  = wid >> 1;
    const int mtx = lane >> 3;
    const int l7  = lane & 7;

    CP_WAIT(1);
    __syncthreads();

    // ---- phase 1: S = Q @ K^T (16 rows x 80 kv per warp) ----
    uint32_t af[4][4];
    #pragma unroll
    for (int k16 = 0; k16 < 4; k16++) {
        const int row   = wm * 16 + (mtx & 1) * 8 + l7;
        const int chunk = k16 * 2 + (mtx >> 1);
        LDMATRIX_X4(af[k16][0], af[k16][1], af[k16][2], af[k16][3],
                    sb + AT_Q + swz((uint32_t)row * 128u + (uint32_t)chunk * 16u));
    }

    float acc[10][4] = {};
    #pragma unroll
    for (int k16 = 0; k16 < 4; k16++) {
        #pragma unroll
        for (int pair = 0; pair < 5; pair++) {
            const int nrow  = wn * 80 + pair * 16 + (mtx >> 1) * 8 + l7;
            const int chunk = k16 * 2 + (mtx & 1);
            uint32_t b0, b1, b2, b3;
            LDMATRIX_X4(b0, b1, b2, b3,
                        sb + AT_K + swz((uint32_t)nrow * 128u + (uint32_t)chunk * 16u));
            uint32_t bfa[2] = {b0, b1}, bfb[2] = {b2, b3};
            MMA_BF16(acc[pair * 2],     af[k16], bfa);
            MMA_BF16(acc[pair * 2 + 1], af[k16], bfb);
        }
    }

    // ---- masks (7x7 window per token) ----
    const int row0 = wm * 16 + (lane >> 2);     // token 0..31
    const int row1 = row0 + 8;
    const int y_a = ty0 + (row0 >> 3), x_a = tx0 + (row0 & 7);
    const int y_b = ty0 + (row1 >> 3), x_b = tx0 + (row1 & 7);
    const int rlo_a = min(max(y_a - 3, 0), 57) - ny0;
    const int clo_a = min(max(x_a - 3, 0), 57) - nx0;
    const int rlo_b = min(max(y_b - 3, 0), 57) - ny0;
    const int clo_b = min(max(x_b - 3, 0), 57) - nx0;

    uint32_t vm_a = 0, vm_b = 0;                // 20 validity bits
    #pragma unroll
    for (int nt = 0; nt < 10; nt++) {
        #pragma unroll
        for (int j = 0; j < 2; j++) {
            const int n = wn * 80 + nt * 8 + (lane & 3) * 2 + j;
            const int r = n >> 4, c = n & 15;
            if (c < 14 && (unsigned)(r - rlo_a) < 7u && (unsigned)(c - clo_a) < 7u)
                vm_a |= 1u << (nt * 2 + j);
            if (c < 14 && (unsigned)(r - rlo_b) < 7u && (unsigned)(c - clo_b) < 7u)
                vm_b |= 1u << (nt * 2 + j);
        }
    }

    // ---- row max ----
    float mx_a = -3e38f, mx_b = -3e38f;
    #pragma unroll
    for (int nt = 0; nt < 10; nt++) {
        #pragma unroll
        for (int j = 0; j < 2; j++) {
            if (vm_a & (1u << (nt * 2 + j))) mx_a = fmaxf(mx_a, acc[nt][j]);
            if (vm_b & (1u << (nt * 2 + j))) mx_b = fmaxf(mx_b, acc[nt][2 + j]);
        }
    }
    mx_a = fmaxf(mx_a, __shfl_xor_sync(0xffffffffu, mx_a, 1));
    mx_a = fmaxf(mx_a, __shfl_xor_sync(0xffffffffu, mx_a, 2));
    mx_b = fmaxf(mx_b, __shfl_xor_sync(0xffffffffu, mx_b, 1));
    mx_b = fmaxf(mx_b, __shfl_xor_sync(0xffffffffu, mx_b, 2));
    if ((lane & 3) == 0) {
        smax[row0 * 2 + wn] = mx_a;
        smax[row1 * 2 + wn] = mx_b;
    }
    __syncthreads();
    const float M_a = fmaxf(smax[row0 * 2], smax[row0 * 2 + 1]);
    const float M_b = fmaxf(smax[row1 * 2], smax[row1 * 2 + 1]);

    // ---- exp + row sum (in place) ----
    const float SC = 0.18033688011112042f;      // 0.125 * log2(e)
    float sm_a = 0.0f, sm_b = 0.0f;
    #pragma unroll
    for (int nt = 0; nt < 10; nt++) {
        #pragma unroll
        for (int j = 0; j < 2; j++) {
            float ea = (vm_a & (1u << (nt * 2 + j)))
                     ? exp2f((acc[nt][j] - M_a) * SC) : 0.0f;
            float eb = (vm_b & (1u << (nt * 2 + j)))
                     ? exp2f((acc[nt][2 + j] - M_b) * SC) : 0.0f;
            acc[nt][j] = ea; acc[nt][2 + j] = eb;
            sm_a += ea; sm_b += eb;
        }
    }
    sm_a += __shfl_xor_sync(0xffffffffu, sm_a, 1);
    sm_a += __shfl_xor_sync(0xffffffffu, sm_a, 2);
    sm_b += __shfl_xor_sync(0xffffffffu, sm_b, 1);
    sm_b += __shfl_xor_sync(0xffffffffu, sm_b, 2);
    if ((lane & 3) == 0) {
        ssum[row0 * 2 + wn] = sm_a;
        ssum[row1 * 2 + wn] = sm_b;
    }

    // ---- pack P fragments (A-frag layout, 5 k16 tiles) ----
    uint32_t pf[5][4];
    #pragma unroll
    for (int s = 0; s < 5; s++) {
        pf[s][0] = packbf(acc[2 * s][0],     acc[2 * s][1]);
        pf[s][1] = packbf(acc[2 * s][2],     acc[2 * s][3]);
        pf[s][2] = packbf(acc[2 * s + 1][0], acc[2 * s + 1][1]);
        pf[s][3] = packbf(acc[2 * s + 1][2], acc[2 * s + 1][3]);
    }

    CP_WAIT(0);
    __syncthreads();     // V ready; K reads done (sred overlays K)

    // ---- phase 2: partial O = P_half @ V_half ----
    float accO[8][4] = {};
    #pragma unroll
    for (int s = 0; s < 5; s++) {
        uint32_t vf[8][2];
        #pragma unroll
        for (int g2 = 0; g2 < 4; g2++) {
            const int kvrow = wn * 80 + s * 16 + (lane & 15);
            const int colb  = (g2 * 16 + (lane >> 4) * 8) * 2;
            LDMATRIX_X4_TRANS(vf[g2 * 2][0], vf[g2 * 2][1],
                              vf[g2 * 2 + 1][0], vf[g2 * 2 + 1][1],
                              sb + AT_V + swz((uint32_t)kvrow * 128u + (uint32_t)colb));
        }
        #pragma unroll
        for (int nt = 0; nt < 8; nt++)
            MMA_BF16(accO[nt], pf[s], vf[nt]);
    }

    // ---- cross-warp reduce (wn=1 -> smem, wn=0 adds + writes) ----
    if (wn == 1) {
        #pragma unroll
        for (int nt = 0; nt < 8; nt++) {
            const int col = nt * 8 + (lane & 3) * 2;
            *reinterpret_cast<float2*>(&sred[row0 * REDW + col]) =
                make_float2(accO[nt][0], accO[nt][1]);
            *reinterpret_cast<float2*>(&sred[row1 * REDW + col]) =
                make_float2(accO[nt][2], accO[nt][3]);
        }
    }
    __syncthreads();

    if (wn == 0) {
        const float inv_a = 1.0f / (ssum[row0 * 2] + ssum[row0 * 2 + 1]);
        const float inv_b = 1.0f / (ssum[row1 * 2] + ssum[row1 * 2 + 1]);
        const size_t t_a = (size_t)b * 4096 + (size_t)(y_a * 64 + x_a);
        const size_t t_b = (size_t)b * 4096 + (size_t)(y_b * 64 + x_b);
        #pragma unroll
        for (int nt = 0; nt < 8; nt++) {
            const int col = nt * 8 + (lane & 3) * 2;
            const float2 ra = *reinterpret_cast<const float2*>(&sred[row0 * REDW + col]);
            const float2 rb = *reinterpret_cast<const float2*>(&sred[row1 * REDW + col]);
            *reinterpret_cast<__nv_bfloat162*>(out + t_a * CDIM + head * 64 + col) =
                __floats2bfloat162_rn((accO[nt][0] + ra.x) * inv_a,
                                      (accO[nt][1] + ra.y) * inv_a);
            *reinterpret_cast<__nv_bfloat162*>(out + t_b * CDIM + head * 64 + col) =
                __floats2bfloat162_rn((accO[nt][2] + rb.x) * inv_b,
                                      (accO[nt][3] + rb.y) * inv_b);
        }
    }
}

// ---------------------------------------------------------------------------
// Launch: 6 kernels.
// ---------------------------------------------------------------------------
extern "C" void kernel_launch(void* const* d_in, const int* in_sizes, int n_in,
                              void* d_out, int out_size)
{
    const float* x       = (const float*)d_in[0];
    const float* norm1_w = (const float*)d_in[1];
    const float* norm2_w = (const float*)d_in[2];
    const float* w_qkv   = (const float*)d_in[3];
    const float* w_proj  = (const float*)d_in[4];
    const float* b_proj  = (const float*)d_in[5];
    const float* ff1_w   = (const float*)d_in[6];
    const float* ff1_b   = (const float*)d_in[7];
    const float* ff2_w   = (const float*)d_in[8];
    const float* ff2_b   = (const float*)d_in[9];
    float* out = (float*)d_out;

    __nv_bfloat16 *p_h, *p_qkv, *p_attn, *p_n2, *p_g;
    __nv_bfloat16 *p_wqkvT, *p_wprojT, *p_ff1T, *p_ff2T;
    float *p_x1;
    cudaGetSymbolAddress((void**)&p_h,      g_h);
    cudaGetSymbolAddress((void**)&p_qkv,    g_qkv);
    cudaGetSymbolAddress((void**)&p_attn,   g_attn);
    cudaGetSymbolAddress((void**)&p_x1,     g_x1);
    cudaGetSymbolAddress((void**)&p_n2,     g_n2);
    cudaGetSymbolAddress((void**)&p_g,      g_g);
    cudaGetSymbolAddress((void**)&p_wqkvT,  g_wqkvT);
    cudaGetSymbolAddress((void**)&p_wprojT, g_wprojT);
    cudaGetSymbolAddress((void**)&p_ff1T,   g_ff1T);
    cudaGetSymbolAddress((void**)&p_ff2T,   g_ff2T);

    cudaFuncSetAttribute(gemm_mma_kernel,
                         cudaFuncAttributeMaxDynamicSharedMemorySize, SM_SIZE);
    cudaFuncSetAttribute(proj_norm_kernel,
                         cudaFuncAttributeMaxDynamicSharedMemorySize, PJ_SIZE);
    cudaFuncSetAttribute(ff1_geglu_kernel,
                         cudaFuncAttributeMaxDynamicSharedMemorySize, F1_SIZE);
    cudaFuncSetAttribute(attn_mma_kernel,
                         cudaFuncAttributeMaxDynamicSharedMemorySize, AT_SIZE);

    // 1. weight transposes (ff1 permuted) + rmsnorm1+rope, one launch
    prep_kernel<<<448 + NTOK / 2, 256>>>(
        w_qkv, p_wqkvT, w_proj, p_wprojT, ff1_w, p_ff1T, ff2_w, p_ff2T,
        x, norm1_w, p_h);

    // 2. qkv = h @ w_qkv -> bf16
    gemm_mma_kernel<<<dim3(QKVN / 64, NTOK / 64), 128, SM_SIZE>>>(
        p_h, p_wqkvT, nullptr, nullptr, nullptr, p_qkv, QKVN, 0);

    // 3. attention (4x8 tiles) -> bf16
    attn_mma_kernel<<<dim3(128, 4, 2), 128, AT_SIZE>>>(p_qkv, p_attn);

    // 4. x1 = x + attn @ w_proj + b_proj;  n2 = rmsnorm(x1, n2w)   (fused)
    proj_norm_kernel<<<NTOK / 64, 256, PJ_SIZE>>>(
        p_attn, p_wprojT, b_proj, x, norm2_w, p_x1, p_n2);

    // 5. g = geglu(n2 @ ff1_w_perm + ff1_b)                        (fused)
    ff1_geglu_kernel<<<dim3(4, NTOK / 64), 256, F1_SIZE>>>(
        p_n2, p_ff1T, ff1_b, p_g);

    // 6. out = x1 + g @ ff2_w + ff2_b
    gemm_mma_kernel<<<dim3(CDIM / 64, NTOK / 64), 128, SM_SIZE>>>(
        p_g, p_ff2T, ff2_b, p_x1, out, nullptr, CDIM, 2);
}

// round 13
// speedup vs baseline: 2.0605x; 1.0005x over previous
#include <cuda_runtime.h>
#include <cuda_bf16.h>
#include <math.h>
#include <stdint.h>

// ---------------------------------------------------------------------------
// Problem constants (B=2, H=W=64, C=256, nh=4, hd=64, k=7)
// ---------------------------------------------------------------------------
#define NTOK   8192
#define CDIM   256
#define GK     256
#define QKVN   768
#define FFN    512
#define KS     7
#define KK     49

// ---------------------------------------------------------------------------
// Scratch (__device__ globals; allocation forbidden)
// ---------------------------------------------------------------------------
__device__ __nv_bfloat16 g_h   [NTOK * CDIM];
__device__ __nv_bfloat16 g_qkv [NTOK * QKVN];
__device__ __nv_bfloat16 g_attn[NTOK * CDIM];
__device__ float         g_x1  [NTOK * CDIM];
__device__ __nv_bfloat16 g_n2  [NTOK * CDIM];
__device__ __nv_bfloat16 g_g   [NTOK * CDIM];
__device__ __nv_bfloat16 g_wqkvT[QKVN * GK];
__device__ __nv_bfloat16 g_wprojT[CDIM * GK];
__device__ __nv_bfloat16 g_ff1T [FFN  * GK];   // PERMUTED column order
__device__ __nv_bfloat16 g_ff2T [CDIM * GK];

// ---------------------------------------------------------------------------
// PTX helpers
// ---------------------------------------------------------------------------
__device__ __forceinline__ uint32_t smem_u32(const void* p) {
    uint32_t a;
    asm("{ .reg .u64 t; cvta.to.shared.u64 t, %1; cvt.u32.u64 %0, t; }"
        : "=r"(a) : "l"(p));
    return a;
}
#define LDMATRIX_X4(r0, r1, r2, r3, a) \
    asm volatile("ldmatrix.sync.aligned.m8n8.x4.shared.b16 {%0,%1,%2,%3}, [%4];" \
                 : "=r"(r0), "=r"(r1), "=r"(r2), "=r"(r3) : "r"(a))
#define LDMATRIX_X4_TRANS(r0, r1, r2, r3, a) \
    asm volatile("ldmatrix.sync.aligned.m8n8.x4.trans.shared.b16 {%0,%1,%2,%3}, [%4];" \
                 : "=r"(r0), "=r"(r1), "=r"(r2), "=r"(r3) : "r"(a))
#define MMA_BF16(d, a, b) \
    asm volatile("mma.sync.aligned.m16n8k16.row.col.f32.bf16.bf16.f32 " \
                 "{%0,%1,%2,%3}, {%4,%5,%6,%7}, {%8,%9}, {%0,%1,%2,%3};" \
                 : "+f"((d)[0]), "+f"((d)[1]), "+f"((d)[2]), "+f"((d)[3]) \
                 : "r"((a)[0]), "r"((a)[1]), "r"((a)[2]), "r"((a)[3]), \
                   "r"((b)[0]), "r"((b)[1]))
#define CP_ASYNC16(dst, src) \
    asm volatile("cp.async.cg.shared.global [%0], [%1], 16;" :: "r"(dst), "l"(src))
#define CP_COMMIT() asm volatile("cp.async.commit_group;" ::: "memory")
#define CP_WAIT(n)  asm volatile("cp.async.wait_group %0;" :: "n"(n) : "memory")

__device__ __forceinline__ uint32_t swz(uint32_t off) { return off ^ ((off >> 3) & 0x70); }
__device__ __forceinline__ uint32_t packbf(float a, float b) {
    __nv_bfloat162 h = __floats2bfloat162_rn(a, b);
    return *reinterpret_cast<uint32_t*>(&h);
}
// ff1 permutation: out col n -> source col of ff1_w
__device__ __forceinline__ int ff1_src(int n) {
    const int within = n & 127, blk = n >> 7;
    return (within < 64) ? (blk * 64 + within) : (256 + blk * 64 + within - 64);
}

// ---------------------------------------------------------------------------
// prep_kernel: weight transposes (ff1 permuted) + rmsnorm1+rope, ONE launch.
// ---------------------------------------------------------------------------
__global__ void prep_kernel(const float* __restrict__ w0, __nv_bfloat16* __restrict__ o0,
                            const float* __restrict__ w1, __nv_bfloat16* __restrict__ o1,
                            const float* __restrict__ w2, __nv_bfloat16* __restrict__ o2,
                            const float* __restrict__ w3, __nv_bfloat16* __restrict__ o3,
                            const float* __restrict__ x,  const float* __restrict__ n1w,
                            __nv_bfloat16* __restrict__ h)
{
    const int bx  = blockIdx.x;
    const int tid = threadIdx.x;
    __shared__ float t[32][33];
    __shared__ float red[2][4];

    if (bx < 448) {
        const int wtile = bx >> 3;
        const int k0    = (bx & 7) * 32;
        const float* w; __nv_bfloat16* o; int N, nb; bool perm = false;
        if      (wtile < 24) { w = w0; o = o0; N = QKVN; nb = wtile;      }
        else if (wtile < 32) { w = w1; o = o1; N = CDIM; nb = wtile - 24; }
        else if (wtile < 48) { w = w2; o = o2; N = FFN;  nb = wtile - 32; perm = true; }
        else                 { w = w3; o = o3; N = CDIM; nb = wtile - 48; }

        const int n0 = nb * 32;
        const int s0 = perm ? ff1_src(n0) : n0;
        const int tx = tid & 31, ty = tid >> 5;
        #pragma unroll
        for (int i = 0; i < 32; i += 8)
            t[ty + i][tx] = w[(size_t)(k0 + ty + i) * N + s0 + tx];
        __syncthreads();
        #pragma unroll
        for (int i = 0; i < 32; i += 8)
            o[(size_t)(n0 + ty + i) * GK + k0 + tx] = __float2bfloat16(t[tx][ty + i]);
        return;
    }

    // ---- rmsnorm1 + rope: 2 tokens per block ----
    const int tok  = (bx - 448) * 2 + (tid >> 7);
    const int i    = tid & 127;
    const int half = tid >> 7;
    float2 v = reinterpret_cast<const float2*>(x + (size_t)tok * CDIM)[i];

    float ss = v.x * v.x + v.y * v.y;
    #pragma unroll
    for (int off = 16; off; off >>= 1)
        ss += __shfl_xor_sync(0xffffffffu, ss, off);
    if ((i & 31) == 0) red[half][i >> 5] = ss;
    __syncthreads();
    const float r = rsqrtf((red[half][0] + red[half][1] + red[half][2] + red[half][3])
                           * (1.0f / CDIM) + 1e-6f);

    const float2 wv = reinterpret_cast<const float2*>(n1w)[i];
    float a = v.x * r * wv.x;
    float b = v.y * r * wv.y;

    const int yy = (tok >> 6) & 63;
    const int xx = tok & 63;
    const int j  = i & 63;
    const float pos = (i < 64) ? (float)yy : (float)xx;
    const float inv = exp2f((float)j * (-13.28771237954945f / 64.0f));
    float c, s;
    sincosf(pos * inv, &s, &c);
    reinterpret_cast<__nv_bfloat162*>(h + (size_t)tok * CDIM)[i] =
        __floats2bfloat162_rn(a * c - b * s, a * s + b * c);
}

// ---------------------------------------------------------------------------
// Generic mma.sync bf16 GEMM: BM=64, BN=64, 128 threads, ring 32KB.
// mode: 0 = bf16 out, 2 = fp32 +bias+residual
// ---------------------------------------------------------------------------
#define GS_STAGE 16384u
#define SM_SIZE  32768

__global__ __launch_bounds__(128, 5)
void gemm_mma_kernel(const __nv_bfloat16* __restrict__ A,
                     const __nv_bfloat16* __restrict__ Bt,
                     const float* __restrict__ bias,
                     const float* __restrict__ residual,
                     float* __restrict__ C,
                     __nv_bfloat16* __restrict__ Cb,
                     int N, int mode)
{
    extern __shared__ __align__(1024) char smem[];
    const uint32_t sb = smem_u32(smem);
    const int tid  = threadIdx.x;
    const int wid  = tid >> 5;
    const int lane = tid & 31;
    const int bm   = blockIdx.y * 64;
    const int bn   = blockIdx.x * 64;
    const int wm   = wid & 1;
    const int wn   = wid >> 1;
    const int lrow = tid >> 3;
    const int lch  = tid & 7;

    #define LOAD_CHUNK(kc, stage) do {                                           \
        const uint32_t s0 = (uint32_t)(stage) * GS_STAGE;                        \
        _Pragma("unroll")                                                        \
        for (int it = 0; it < 4; it++) {                                         \
            const int row = it * 16 + lrow;                                      \
            uint32_t off = swz((uint32_t)row * 128u + (uint32_t)lch * 16u);      \
            CP_ASYNC16(sb + s0 + off,                                            \
                       A  + (size_t)(bm + row) * GK + (kc) * 64 + lch * 8);      \
            CP_ASYNC16(sb + s0 + 8192u + off,                                    \
                       Bt + (size_t)(bn + row) * GK + (kc) * 64 + lch * 8);      \
        }                                                                        \
        CP_COMMIT();                                                             \
    } while (0)

    LOAD_CHUNK(0, 0);
    LOAD_CHUNK(1, 1);

    float acc[2][4][4] = {};
    const int mtx = lane >> 3;
    const int l7  = lane & 7;

    #pragma unroll
    for (int kc = 0; kc < 4; kc++) {
        if (kc < 3) CP_WAIT(1); else CP_WAIT(0);
        __syncthreads();
        const uint32_t sA = sb + (uint32_t)(kc & 1) * GS_STAGE;
        const uint32_t sB = sA + 8192u;

        #pragma unroll
        for (int s16 = 0; s16 < 4; s16++) {
            const int chunk0 = s16 * 2;
            uint32_t af[2][4];
            #pragma unroll
            for (int mt = 0; mt < 2; mt++) {
                const int row   = wm * 32 + mt * 16 + (mtx & 1) * 8 + l7;
                const int chunk = chunk0 + (mtx >> 1);
                LDMATRIX_X4(af[mt][0], af[mt][1], af[mt][2], af[mt][3],
                            sA + swz((uint32_t)row * 128u + (uint32_t)chunk * 16u));
            }
            uint32_t bf[4][2];
            #pragma unroll
            for (int pair = 0; pair < 2; pair++) {
                const int nrow  = wn * 32 + pair * 16 + (mtx >> 1) * 8 + l7;
                const int chunk = chunk0 + (mtx & 1);
                LDMATRIX_X4(bf[pair * 2][0], bf[pair * 2][1],
                            bf[pair * 2 + 1][0], bf[pair * 2 + 1][1],
                            sB + swz((uint32_t)nrow * 128u + (uint32_t)chunk * 16u));
            }
            #pragma unroll
            for (int mt = 0; mt < 2; mt++)
                #pragma unroll
                for (int nt = 0; nt < 4; nt++)
                    MMA_BF16(acc[mt][nt], af[mt], bf[nt]);
        }
        __syncthreads();
        if (kc < 2) LOAD_CHUNK(kc + 2, kc & 1);
    }
    #undef LOAD_CHUNK

    const int rbase = bm + wm * 32 + (lane >> 2);
    const int cbase = bn + wn * 32 + (lane & 3) * 2;
    #pragma unroll
    for (int mt = 0; mt < 2; mt++) {
        #pragma unroll
        for (int half = 0; half < 2; half++) {
            const int row = rbase + mt * 16 + half * 8;
            #pragma unroll
            for (int nt = 0; nt < 4; nt++) {
                const int col = cbase + nt * 8;
                float ox = acc[mt][nt][half * 2];
                float oy = acc[mt][nt][half * 2 + 1];
                const size_t idx = (size_t)row * N + col;
                if (mode == 0) {
                    *reinterpret_cast<__nv_bfloat162*>(&Cb[idx]) =
                        __floats2bfloat162_rn(ox, oy);
                } else {
                    ox += bias[col];
                    oy += bias[col + 1];
                    const float2 rr = *reinterpret_cast<const float2*>(&residual[idx]);
                    *reinterpret_cast<float2*>(&C[idx]) =
                        make_float2(ox + rr.x, oy + rr.y);
                }
            }
        }
    }
}

// ---------------------------------------------------------------------------
// proj GEMM + residual + fused RMSNorm2 epilogue. v2: BM=32, BN=256,
// 256 threads = 8 warps of 32rows x 32cols -> grid 256, 2 CTAs/SM.
// ---------------------------------------------------------------------------
#define PJ_STG  36864u            // 4KB A + 32KB B per stage
#define PJ_SIZE 73728

__global__ __launch_bounds__(256, 2)
void proj_norm_kernel(const __nv_bfloat16* __restrict__ A,
                      const __nv_bfloat16* __restrict__ Bt,
                      const float* __restrict__ bias,
                      const float* __restrict__ residual,
                      const float* __restrict__ n2w,
                      float* __restrict__ X1,
                      __nv_bfloat16* __restrict__ N2)
{
    extern __shared__ __align__(1024) char smem[];
    const uint32_t sb = smem_u32(smem);
    float* sredn = reinterpret_cast<float*>(smem);    // [32][8] (stage0, dead)
    const int tid  = threadIdx.x;
    const int wid  = tid >> 5;                        // wn = wid, 32 cols each
    const int lane = tid & 31;
    const int bm   = blockIdx.x * 32;
    const int lrow = tid >> 3;                        // 0..31
    const int lch  = tid & 7;

    #define PJ_LOAD(kc, stage) do {                                              \
        const uint32_t s0 = (uint32_t)(stage) * PJ_STG;                          \
        {                                                                        \
            uint32_t off = swz((uint32_t)lrow * 128u + (uint32_t)lch * 16u);     \
            CP_ASYNC16(sb + s0 + off,                                            \
                       A + (size_t)(bm + lrow) * GK + (kc) * 64 + lch * 8);      \
        }                                                                        \
        _Pragma("unroll")                                                        \
        for (int it = 0; it < 8; it++) {                                         \
            const int row = it * 32 + lrow;                                      \
            uint32_t off = swz((uint32_t)row * 128u + (uint32_t)lch * 16u);      \
            CP_ASYNC16(sb + s0 + 4096u + off,                                    \
                       Bt + (size_t)row * GK + (kc) * 64 + lch * 8);             \
        }                                                                        \
        CP_COMMIT();                                                             \
    } while (0)

    PJ_LOAD(0, 0);
    PJ_LOAD(1, 1);

    float acc[2][4][4] = {};
    const int mtx = lane >> 3;
    const int l7  = lane & 7;

    #pragma unroll
    for (int kc = 0; kc < 4; kc++) {
        if (kc < 3) CP_WAIT(1); else CP_WAIT(0);
        __syncthreads();
        const uint32_t sA = sb + (uint32_t)(kc & 1) * PJ_STG;
        const uint32_t sB = sA + 4096u;

        #pragma unroll
        for (int s16 = 0; s16 < 4; s16++) {
            const int chunk0 = s16 * 2;
            uint32_t af[2][4];
            #pragma unroll
            for (int mt = 0; mt < 2; mt++) {
                const int row   = mt * 16 + (mtx & 1) * 8 + l7;
                const int chunk = chunk0 + (mtx >> 1);
                LDMATRIX_X4(af[mt][0], af[mt][1], af[mt][2], af[mt][3],
                            sA + swz((uint32_t)row * 128u + (uint32_t)chunk * 16u));
            }
            uint32_t bf[4][2];
            #pragma unroll
            for (int pair = 0; pair < 2; pair++) {
                const int nrow  = wid * 32 + pair * 16 + (mtx >> 1) * 8 + l7;
                const int chunk = chunk0 + (mtx & 1);
                LDMATRIX_X4(bf[pair * 2][0], bf[pair * 2][1],
                            bf[pair * 2 + 1][0], bf[pair * 2 + 1][1],
                            sB + swz((uint32_t)nrow * 128u + (uint32_t)chunk * 16u));
            }
            #pragma unroll
            for (int mt = 0; mt < 2; mt++)
                #pragma unroll
                for (int nt = 0; nt < 4; nt++)
                    MMA_BF16(acc[mt][nt], af[mt], bf[nt]);
        }
        __syncthreads();
        if (kc < 2) PJ_LOAD(kc + 2, kc & 1);
    }
    #undef PJ_LOAD

    // ---- epilogue: bias + residual -> x1; rowwise sumsq across 8 warps ----
    const int rl   = lane >> 2;                  // local row base 0..7
    const int cbse = wid * 32 + (lane & 3) * 2;
    float ss[2][2] = {};
    #pragma unroll
    for (int mt = 0; mt < 2; mt++) {
        #pragma unroll
        for (int half = 0; half < 2; half++) {
            const int row = bm + rl + mt * 16 + half * 8;
            #pragma unroll
            for (int nt = 0; nt < 4; nt++) {
                const int col = cbse + nt * 8;
                float ox = acc[mt][nt][half * 2]     + bias[col];
                float oy = acc[mt][nt][half * 2 + 1] + bias[col + 1];
                const size_t idx = (size_t)row * CDIM + col;
                const float2 rr = *reinterpret_cast<const float2*>(&residual[idx]);
                ox += rr.x; oy += rr.y;
                *reinterpret_cast<float2*>(&X1[idx]) = make_float2(ox, oy);
                acc[mt][nt][half * 2]     = ox;
                acc[mt][nt][half * 2 + 1] = oy;
                ss[mt][half] += ox * ox + oy * oy;
            }
        }
    }
    #pragma unroll
    for (int mt = 0; mt < 2; mt++)
        #pragma unroll
        for (int half = 0; half < 2; half++) {
            float v = ss[mt][half];
            v += __shfl_xor_sync(0xffffffffu, v, 1);
            v += __shfl_xor_sync(0xffffffffu, v, 2);
            if ((lane & 3) == 0)
                sredn[(rl + mt * 16 + half * 8) * 8 + wid] = v;
        }
    __syncthreads();

    #pragma unroll
    for (int mt = 0; mt < 2; mt++) {
        #pragma unroll
        for (int half = 0; half < 2; half++) {
            const int rloc = rl + mt * 16 + half * 8;
            float tot = 0.0f;
            #pragma unroll
            for (int wq = 0; wq < 8; wq++) tot += sredn[rloc * 8 + wq];
            const float r = rsqrtf(tot * (1.0f / CDIM) + 1e-6f);
            const int row = bm + rloc;
            #pragma unroll
            for (int nt = 0; nt < 4; nt++) {
                const int col = cbse + nt * 8;
                const float2 wv = *reinterpret_cast<const float2*>(&n2w[col]);
                *reinterpret_cast<__nv_bfloat162*>(&N2[(size_t)row * CDIM + col]) =
                    __floats2bfloat162_rn(acc[mt][nt][half * 2] * r * wv.x,
                                          acc[mt][nt][half * 2 + 1] * r * wv.y);
            }
        }
    }
}

// ---------------------------------------------------------------------------
// ff1 GEMM (permuted columns) + bias + fused GeGLU epilogue (unchanged R11).
// ---------------------------------------------------------------------------
#define F1_STG  24576u
#define F1_SIZE 49152

__global__ __launch_bounds__(256, 3)
void ff1_geglu_kernel(const __nv_bfloat16* __restrict__ A,
                      const __nv_bfloat16* __restrict__ Bt,
                      const float* __restrict__ bias,
                      __nv_bfloat16* __restrict__ G)
{
    extern __shared__ __align__(1024) char smem[];
    const uint32_t sb = smem_u32(smem);
    float* vred = reinterpret_cast<float*>(smem);
    const int tid  = threadIdx.x;
    const int wid  = tid >> 5;
    const int lane = tid & 31;
    const int bm   = blockIdx.y * 64;
    const int bn   = blockIdx.x * 128;
    const int wm   = wid & 1;
    const int wn   = wid >> 1;
    const int lrow = tid >> 3;
    const int lch  = tid & 7;

    #define F1_LOAD(kc, stage) do {                                              \
        const uint32_t s0 = (uint32_t)(stage) * F1_STG;                          \
        _Pragma("unroll")                                                        \
        for (int it = 0; it < 2; it++) {                                         \
            const int row = it * 32 + lrow;                                      \
            uint32_t off = swz((uint32_t)row * 128u + (uint32_t)lch * 16u);      \
            CP_ASYNC16(sb + s0 + off,                                            \
                       A + (size_t)(bm + row) * GK + (kc) * 64 + lch * 8);       \
        }                                                                        \
        _Pragma("unroll")                                                        \
        for (int it = 0; it < 4; it++) {                                         \
            const int row = it * 32 + lrow;                                      \
            uint32_t off = swz((uint32_t)row * 128u + (uint32_t)lch * 16u);      \
            CP_ASYNC16(sb + s0 + 8192u + off,                                    \
                       Bt + (size_t)(bn + row) * GK + (kc) * 64 + lch * 8);      \
        }                                                                        \
        CP_COMMIT();                                                             \
    } while (0)

    F1_LOAD(0, 0);
    F1_LOAD(1, 1);

    float acc[2][4][4] = {};
    const int mtx = lane >> 3;
    const int l7  = lane & 7;

    #pragma unroll
    for (int kc = 0; kc < 4; kc++) {
        if (kc < 3) CP_WAIT(1); else CP_WAIT(0);
        __syncthreads();
        const uint32_t sA = sb + (uint32_t)(kc & 1) * F1_STG;
        const uint32_t sB = sA + 8192u;

        #pragma unroll
        for (int s16 = 0; s16 < 4; s16++) {
            const int chunk0 = s16 * 2;
            uint32_t af[2][4];
            #pragma unroll
            for (int mt = 0; mt < 2; mt++) {
                const int row   = wm * 32 + mt * 16 + (mtx & 1) * 8 + l7;
                const int chunk = chunk0 + (mtx >> 1);
                LDMATRIX_X4(af[mt][0], af[mt][1], af[mt][2], af[mt][3],
                            sA + swz((uint32_t)row * 128u + (uint32_t)chunk * 16u));
            }
            uint32_t bf[4][2];
            #pragma unroll
            for (int pair = 0; pair < 2; pair++) {
                const int nrow  = wn * 32 + pair * 16 + (mtx >> 1) * 8 + l7;
                const int chunk = chunk0 + (mtx & 1);
                LDMATRIX_X4(bf[pair * 2][0], bf[pair * 2][1],
                            bf[pair * 2 + 1][0], bf[pair * 2 + 1][1],
                            sB + swz((uint32_t)nrow * 128u + (uint32_t)chunk * 16u));
            }
            #pragma unroll
            for (int mt = 0; mt < 2; mt++)
                #pragma unroll
                for (int nt = 0; nt < 4; nt++)
                    MMA_BF16(acc[mt][nt], af[mt], bf[nt]);
        }
        __syncthreads();
        if (kc < 2) F1_LOAD(kc + 2, kc & 1);
    }
    #undef F1_LOAD

    const int rl   = wm * 32 + (lane >> 2);
    const int cloc = wn * 32 + (lane & 3) * 2;
    #pragma unroll
    for (int mt = 0; mt < 2; mt++) {
        #pragma unroll
        for (int half = 0; half < 2; half++) {
            #pragma unroll
            for (int nt = 0; nt < 4; nt++) {
                const int c = cloc + nt * 8;
                acc[mt][nt][half * 2]     += bias[ff1_src(bn + c)];
                acc[mt][nt][half * 2 + 1] += bias[ff1_src(bn + c + 1)];
            }
        }
    }
    if (wn >= 2) {
        #pragma unroll
        for (int mt = 0; mt < 2; mt++)
            #pragma unroll
            for (int half = 0; half < 2; half++) {
                const int row = rl + mt * 16 + half * 8;
                #pragma unroll
                for (int nt = 0; nt < 4; nt++) {
                    const int j = cloc + nt * 8 - 64;
                    *reinterpret_cast<float2*>(&vred[row * 64 + j]) =
                        make_float2(acc[mt][nt][half * 2], acc[mt][nt][half * 2 + 1]);
                }
            }
    }
    __syncthreads();
    if (wn < 2) {
        #pragma unroll
        for (int mt = 0; mt < 2; mt++)
            #pragma unroll
            for (int half = 0; half < 2; half++) {
                const int row = rl + mt * 16 + half * 8;
                #pragma unroll
                for (int nt = 0; nt < 4; nt++) {
                    const int j = cloc + nt * 8;
                    const float2 vv = *reinterpret_cast<const float2*>(&vred[row * 64 + j]);
                    const float g0 = acc[mt][nt][half * 2];
                    const float g1 = acc[mt][nt][half * 2 + 1];
                    const float e0 = 0.5f * g0 * (1.0f + erff(g0 * 0.70710678118654752f));
                    const float e1 = 0.5f * g1 * (1.0f + erff(g1 * 0.70710678118654752f));
                    *reinterpret_cast<__nv_bfloat162*>(
                        &G[(size_t)(bm + row) * CDIM + blockIdx.x * 64 + j]) =
                        __floats2bfloat162_rn(e0 * vv.x, e1 * vv.y);
                }
            }
    }
}

// ---------------------------------------------------------------------------
// Neighborhood attention, 4x8 token tile, halo 10x14 -> 160 kv (R12).
// ---------------------------------------------------------------------------
#define AT_Q    0
#define AT_K    4096
#define AT_V    24576
#define AT_RED  4096
#define AT_MAX  45056
#define AT_SUM  45312
#define AT_SIZE 45568
#define REDW    68

__global__ __launch_bounds__(128, 5)
void attn_mma_kernel(const __nv_bfloat16* __restrict__ qkv,
                     __nv_bfloat16* __restrict__ out)
{
    extern __shared__ __align__(1024) char smem[];
    const uint32_t sb = smem_u32(smem);
    float* smax = reinterpret_cast<float*>(smem + AT_MAX);
    float* ssum = reinterpret_cast<float*>(smem + AT_SUM);
    float* sred = reinterpret_cast<float*>(smem + AT_RED);

    const int tid  = threadIdx.x;
    const int wid  = tid >> 5;
    const int lane = tid & 31;
    const int head = blockIdx.y;
    const int b    = blockIdx.z;
    const int ty0  = (blockIdx.x >> 3) * 4;
    const int tx0  = (blockIdx.x & 7) * 8;
    const int ny0  = min(max(ty0 - 3, 0), 54);
    const int nx0  = min(max(tx0 - 3, 0), 50);

    const __nv_bfloat16* base = qkv + (size_t)b * 4096 * QKVN + head * 64;

    #pragma unroll
    for (int i = 0; i < 2; i++) {
        const int idx = i * 128 + tid;
        const int m = idx >> 3, ch = idx & 7;
        const int y = ty0 + (m >> 3), x = tx0 + (m & 7);
        uint32_t off = swz((uint32_t)m * 128u + (uint32_t)ch * 16u);
        CP_ASYNC16(sb + AT_Q + off, base + (size_t)(y * 64 + x) * QKVN + ch * 8);
    }
    CP_COMMIT();
    #pragma unroll
    for (int i = 0; i < 10; i++) {
        const int idx = i * 128 + tid;
        const int kv = idx >> 3, ch = idx & 7;
        const int r = kv >> 4, c = kv & 15;
        uint32_t off = swz((uint32_t)kv * 128u + (uint32_t)ch * 16u);
        if (c < 14)
            CP_ASYNC16(sb + AT_K + off,
                       base + (size_t)((ny0 + r) * 64 + nx0 + c) * QKVN + CDIM + ch * 8);
        else
            *reinterpret_cast<uint4*>(smem + AT_K + off) = make_uint4(0, 0, 0, 0);
    }
    CP_COMMIT();
    #pragma unroll
    for (int i = 0; i < 10; i++) {
        const int idx = i * 128 + tid;
        const int kv = idx >> 3, ch = idx & 7;
        const int r = kv >> 4, c = kv & 15;
        uint32_t off = swz((uint32_t)kv * 128u + (uint32_t)ch * 16u);
        if (c < 14)
            CP_ASYNC16(sb + AT_V + off,
                       base + (size_t)((ny0 + r) * 64 + nx0 + c) * QKVN + 2 * CDIM + ch * 8);
        else
            *reinterpret_cast<uint4*>(smem + AT_V + off) = make_uint4(0, 0, 0, 0);
    }
    CP_COMMIT();

    const int wm  = wid & 1;
    const int wn  = wid >> 1;
    const int mtx = lane >> 3;
    const int l7  = lane & 7;

    CP_WAIT(1);
    __syncthreads();

    uint32_t af[4][4];
    #pragma unroll
    for (int k16 = 0; k16 < 4; k16++) {
        const int row   = wm * 16 + (mtx & 1) * 8 + l7;
        const int chunk = k16 * 2 + (mtx >> 1);
        LDMATRIX_X4(af[k16][0], af[k16][1], af[k16][2], af[k16][3],
                    sb + AT_Q + swz((uint32_t)row * 128u + (uint32_t)chunk * 16u));
    }

    float acc[10][4] = {};
    #pragma unroll
    for (int k16 = 0; k16 < 4; k16++) {
        #pragma unroll
        for (int pair = 0; pair < 5; pair++) {
            const int nrow  = wn * 80 + pair * 16 + (mtx >> 1) * 8 + l7;
            const int chunk = k16 * 2 + (mtx & 1);
            uint32_t b0, b1, b2, b3;
            LDMATRIX_X4(b0, b1, b2, b3,
                        sb + AT_K + swz((uint32_t)nrow * 128u + (uint32_t)chunk * 16u));
            uint32_t bfa[2] = {b0, b1}, bfb[2] = {b2, b3};
            MMA_BF16(acc[pair * 2],     af[k16], bfa);
            MMA_BF16(acc[pair * 2 + 1], af[k16], bfb);
        }
    }

    const int row0 = wm * 16 + (lane >> 2);
    const int row1 = row0 + 8;
    const int y_a = ty0 + (row0 >> 3), x_a = tx0 + (row0 & 7);
    const int y_b = ty0 + (row1 >> 3), x_b = tx0 + (row1 & 7);
    const int rlo_a = min(max(y_a - 3, 0), 57) - ny0;
    const int clo_a = min(max(x_a - 3, 0), 57) - nx0;
    const int rlo_b = min(max(y_b - 3, 0), 57) - ny0;
    const int clo_b = min(max(x_b - 3, 0), 57) - nx0;

    uint32_t vm_a = 0, vm_b = 0;
    #pragma unroll
    for (int nt = 0; nt < 10; nt++) {
        #pragma unroll
        for (int j = 0; j < 2; j++) {
            const int n = wn * 80 + nt * 8 + (lane & 3) * 2 + j;
            const int r = n >> 4, c = n & 15;
            if (c < 14 && (unsigned)(r - rlo_a) < 7u && (unsigned)(c - clo_a) < 7u)
                vm_a |= 1u << (nt * 2 + j);
            if (c < 14 && (unsigned)(r - rlo_b) < 7u && (unsigned)(c - clo_b) < 7u)
                vm_b |= 1u << (nt * 2 + j);
        }
    }

    float mx_a = -3e38f, mx_b = -3e38f;
    #pragma unroll
    for (int nt = 0; nt < 10; nt++) {
        #pragma unroll
        for (int j = 0; j < 2; j++) {
            if (vm_a & (1u << (nt * 2 + j))) mx_a = fmaxf(mx_a, acc[nt][j]);
            if (vm_b & (1u << (nt * 2 + j))) mx_b = fmaxf(mx_b, acc[nt][2 + j]);
        }
    }
    mx_a = fmaxf(mx_a, __shfl_xor_sync(0xffffffffu, mx_a, 1));
    mx_a = fmaxf(mx_a, __shfl_xor_sync(0xffffffffu, mx_a, 2));
    mx_b = fmaxf(mx_b, __shfl_xor_sync(0xffffffffu, mx_b, 1));
    mx_b = fmaxf(mx_b, __shfl_xor_sync(0xffffffffu, mx_b, 2));
    if ((lane & 3) == 0) {
        smax[row0 * 2 + wn] = mx_a;
        smax[row1 * 2 + wn] = mx_b;
    }
    __syncthreads();
    const float M_a = fmaxf(smax[row0 * 2], smax[row0 * 2 + 1]);
    const float M_b = fmaxf(smax[row1 * 2], smax[row1 * 2 + 1]);

    const float SC = 0.18033688011112042f;
    float sm_a = 0.0f, sm_b = 0.0f;
    #pragma unroll
    for (int nt = 0; nt < 10; nt++) {
        #pragma unroll
        for (int j = 0; j < 2; j++) {
            float ea = (vm_a & (1u << (nt * 2 + j)))
                     ? exp2f((acc[nt][j] - M_a) * SC) : 0.0f;
            float eb = (vm_b & (1u << (nt * 2 + j)))
                     ? exp2f((acc[nt][2 + j] - M_b) * SC) : 0.0f;
            acc[nt][j] = ea; acc[nt][2 + j] = eb;
            sm_a += ea; sm_b += eb;
        }
    }
    sm_a += __shfl_xor_sync(0xffffffffu, sm_a, 1);
    sm_a += __shfl_xor_sync(0xffffffffu, sm_a, 2);
    sm_b += __shfl_xor_sync(0xffffffffu, sm_b, 1);
    sm_b += __shfl_xor_sync(0xffffffffu, sm_b, 2);
    if ((lane & 3) == 0) {
        ssum[row0 * 2 + wn] = sm_a;
        ssum[row1 * 2 + wn] = sm_b;
    }

    uint32_t pf[5][4];
    #pragma unroll
    for (int s = 0; s < 5; s++) {
        pf[s][0] = packbf(acc[2 * s][0],     acc[2 * s][1]);
        pf[s][1] = packbf(acc[2 * s][2],     acc[2 * s][3]);
        pf[s][2] = packbf(acc[2 * s + 1][0], acc[2 * s + 1][1]);
        pf[s][3] = packbf(acc[2 * s + 1][2], acc[2 * s + 1][3]);
    }

    CP_WAIT(0);
    __syncthreads();

    float accO[8][4] = {};
    #pragma unroll
    for (int s = 0; s < 5; s++) {
        uint32_t vf[8][2];
        #pragma unroll
        for (int g2 = 0; g2 < 4; g2++) {
            const int kvrow = wn * 80 + s * 16 + (lane & 15);
            const int colb  = (g2 * 16 + (lane >> 4) * 8) * 2;
            LDMATRIX_X4_TRANS(vf[g2 * 2][0], vf[g2 * 2][1],
                              vf[g2 * 2 + 1][0], vf[g2 * 2 + 1][1],
                              sb + AT_V + swz((uint32_t)kvrow * 128u + (uint32_t)colb));
        }
        #pragma unroll
        for (int nt = 0; nt < 8; nt++)
            MMA_BF16(accO[nt], pf[s], vf[nt]);
    }

    if (wn == 1) {
        #pragma unroll
        for (int nt = 0; nt < 8; nt++) {
            const int col = nt * 8 + (lane & 3) * 2;
            *reinterpret_cast<float2*>(&sred[row0 * REDW + col]) =
                make_float2(accO[nt][0], accO[nt][1]);
            *reinterpret_cast<float2*>(&sred[row1 * REDW + col]) =
                make_float2(accO[nt][2], accO[nt][3]);
        }
    }
    __syncthreads();

    if (wn == 0) {
        const float inv_a = 1.0f / (ssum[row0 * 2] + ssum[row0 * 2 + 1]);
        const float inv_b = 1.0f / (ssum[row1 * 2] + ssum[row1 * 2 + 1]);
        const size_t t_a = (size_t)b * 4096 + (size_t)(y_a * 64 + x_a);
        const size_t t_b = (size_t)b * 4096 + (size_t)(y_b * 64 + x_b);
        #pragma unroll
        for (int nt = 0; nt < 8; nt++) {
            const int col = nt * 8 + (lane & 3) * 2;
            const float2 ra = *reinterpret_cast<const float2*>(&sred[row0 * REDW + col]);
            const float2 rb = *reinterpret_cast<const float2*>(&sred[row1 * REDW + col]);
            *reinterpret_cast<__nv_bfloat162*>(out + t_a * CDIM + head * 64 + col) =
                __floats2bfloat162_rn((accO[nt][0] + ra.x) * inv_a,
                                      (accO[nt][1] + ra.y) * inv_a);
            *reinterpret_cast<__nv_bfloat162*>(out + t_b * CDIM + head * 64 + col) =
                __floats2bfloat162_rn((accO[nt][2] + rb.x) * inv_b,
                                      (accO[nt][3] + rb.y) * inv_b);
        }
    }
}

// ---------------------------------------------------------------------------
// Launch: 6 kernels.
// ---------------------------------------------------------------------------
extern "C" void kernel_launch(void* const* d_in, const int* in_sizes, int n_in,
                              void* d_out, int out_size)
{
    const float* x       = (const float*)d_in[0];
    const float* norm1_w = (const float*)d_in[1];
    const float* norm2_w = (const float*)d_in[2];
    const float* w_qkv   = (const float*)d_in[3];
    const float* w_proj  = (const float*)d_in[4];
    const float* b_proj  = (const float*)d_in[5];
    const float* ff1_w   = (const float*)d_in[6];
    const float* ff1_b   = (const float*)d_in[7];
    const float* ff2_w   = (const float*)d_in[8];
    const float* ff2_b   = (const float*)d_in[9];
    float* out = (float*)d_out;

    __nv_bfloat16 *p_h, *p_qkv, *p_attn, *p_n2, *p_g;
    __nv_bfloat16 *p_wqkvT, *p_wprojT, *p_ff1T, *p_ff2T;
    float *p_x1;
    cudaGetSymbolAddress((void**)&p_h,      g_h);
    cudaGetSymbolAddress((void**)&p_qkv,    g_qkv);
    cudaGetSymbolAddress((void**)&p_attn,   g_attn);
    cudaGetSymbolAddress((void**)&p_x1,     g_x1);
    cudaGetSymbolAddress((void**)&p_n2,     g_n2);
    cudaGetSymbolAddress((void**)&p_g,      g_g);
    cudaGetSymbolAddress((void**)&p_wqkvT,  g_wqkvT);
    cudaGetSymbolAddress((void**)&p_wprojT, g_wprojT);
    cudaGetSymbolAddress((void**)&p_ff1T,   g_ff1T);
    cudaGetSymbolAddress((void**)&p_ff2T,   g_ff2T);

    cudaFuncSetAttribute(gemm_mma_kernel,
                         cudaFuncAttributeMaxDynamicSharedMemorySize, SM_SIZE);
    cudaFuncSetAttribute(proj_norm_kernel,
                         cudaFuncAttributeMaxDynamicSharedMemorySize, PJ_SIZE);
    cudaFuncSetAttribute(ff1_geglu_kernel,
                         cudaFuncAttributeMaxDynamicSharedMemorySize, F1_SIZE);
    cudaFuncSetAttribute(attn_mma_kernel,
                         cudaFuncAttributeMaxDynamicSharedMemorySize, AT_SIZE);

    // 1. weight transposes (ff1 permuted) + rmsnorm1+rope, one launch
    prep_kernel<<<448 + NTOK / 2, 256>>>(
        w_qkv, p_wqkvT, w_proj, p_wprojT, ff1_w, p_ff1T, ff2_w, p_ff2T,
        x, norm1_w, p_h);

    // 2. qkv = h @ w_qkv -> bf16
    gemm_mma_kernel<<<dim3(QKVN / 64, NTOK / 64), 128, SM_SIZE>>>(
        p_h, p_wqkvT, nullptr, nullptr, nullptr, p_qkv, QKVN, 0);

    // 3. attention (4x8 tiles) -> bf16
    attn_mma_kernel<<<dim3(128, 4, 2), 128, AT_SIZE>>>(p_qkv, p_attn);

    // 4. x1 = x + attn @ w_proj + b_proj;  n2 = rmsnorm(x1, n2w)   (fused, BM=32)
    proj_norm_kernel<<<NTOK / 32, 256, PJ_SIZE>>>(
        p_attn, p_wprojT, b_proj, x, norm2_w, p_x1, p_n2);

    // 5. g = geglu(n2 @ ff1_w_perm + ff1_b)                        (fused)
    ff1_geglu_kernel<<<dim3(4, NTOK / 64), 256, F1_SIZE>>>(
        p_n2, p_ff1T, ff1_b, p_g);

    // 6. out = x1 + g @ ff2_w + ff2_b
    gemm_mma_kernel<<<dim3(CDIM / 64, NTOK / 64), 128, SM_SIZE>>>(
        p_g, p_ff2T, ff2_b, p_x1, out, nullptr, CDIM, 2);
}